// round 9
// baseline (speedup 1.0000x reference)
#include <cuda_runtime.h>
#include <cuda_bf16.h>
#include <cstdint>
#include <math.h>

#define NN   50000
#define EE   800000
#define FIN  256
#define HID  256
#define FOUT 128

// ---------------- scratch (device globals; no allocation allowed) ----------
__device__ float g_bufA[4][NN * HID];        // gemm1 out (fp32); [0],[2] reused for residual
__device__ float g_bufC[4][NN * FOUT];       // layer-2 gemm out for agg2
__device__ uint2 g_xh[4][NN * FIN / 4];      // pre-split x (bf16 hi)
__device__ uint2 g_xl[4][NN * FIN / 4];      // pre-split x (bf16 lo)
__device__ uint2 g_bh[4][NN * HID / 4];      // pre-split hidden (bf16 hi)
__device__ uint2 g_bl[4][NN * HID / 4];      // pre-split hidden (bf16 lo)
__device__ uint16_t g_wth[4 * 65536 + 6 * 32768];  // W^T hi
__device__ uint16_t g_wtl[4 * 65536 + 6 * 32768];  // W^T lo
__device__ float g_dinv[4][NN];
__device__ float g_deginv[4][NN];
__device__ int   g_counts[4][NN];
__device__ int   g_cursor[4][NN];
__device__ int   g_rowptr[4][NN + 1];
__device__ int   g_col[4][EE];
__device__ float g_coef[4][EE];
__device__ int   g_fmt64;

struct Ptr4 { const float* p[4]; };

// ==================== helpers ================================================
__device__ __forceinline__ void cp16(uint32_t dst, const void* src, int nbytes) {
    asm volatile("cp.async.cg.shared.global [%0], [%1], 16, %2;"
                 :: "r"(dst), "l"(src), "r"(nbytes));
}

__device__ __forceinline__ void mma_bf16(float* d, const uint32_t* a, const uint32_t* b) {
    asm volatile(
        "mma.sync.aligned.m16n8k16.row.col.f32.bf16.bf16.f32 "
        "{%0,%1,%2,%3}, {%4,%5,%6,%7}, {%8,%9}, {%0,%1,%2,%3};"
        : "+f"(d[0]), "+f"(d[1]), "+f"(d[2]), "+f"(d[3])
        : "r"(a[0]), "r"(a[1]), "r"(a[2]), "r"(a[3]), "r"(b[0]), "r"(b[1]));
}

#define LDSM_X4(r0, r1, r2, r3, addr) \
    asm volatile("ldmatrix.sync.aligned.m8n8.x4.shared.b16 {%0,%1,%2,%3}, [%4];" \
                 : "=r"(r0), "=r"(r1), "=r"(r2), "=r"(r3) : "r"(addr))

__device__ __forceinline__ uint32_t pack_bf16(float x, float y) {
    uint32_t r;
    asm("cvt.rn.bf16x2.f32 %0, %1, %2;" : "=r"(r) : "f"(y), "f"(x));
    return r;
}
__device__ __forceinline__ float bfLO(uint32_t w) { return __uint_as_float(w << 16); }
__device__ __forceinline__ float bfHI(uint32_t w) { return __uint_as_float(w & 0xffff0000u); }

__device__ __forceinline__ uint32_t smem_u32(const void* p) {
    uint32_t a;
    asm("{ .reg .u64 t; cvta.to.shared.u64 t, %1; cvt.u32.u64 %0, t; }"
        : "=r"(a) : "l"(p));
    return a;
}

// ==================== pre-split bf16 GEMM (mma.sync + ldmatrix) =============
#define LDW 20                     // words per row (16 data + 4 pad); 80B row stride
#define TILE_WORDS (128 * LDW)
#define SMEM_GEMM (2 * 4 * TILE_WORDS * 4)   // 81920 B

struct GArgs {
    const uint16_t *ah[3], *al[3], *wh[3], *wl[3];
    float* c[3];
};

template<int NC>
__global__ void __launch_bounds__(256, 1)
k_gemm(GArgs g, int M)
{
    const int z = blockIdx.z;
    const uint16_t* __restrict__ Ah = g.ah[z];
    const uint16_t* __restrict__ Al = g.al[z];
    const uint16_t* __restrict__ Wh = g.wh[z];
    const uint16_t* __restrict__ Wl = g.wl[z];
    float* __restrict__ C = g.c[z];

    extern __shared__ uint32_t smw[];
    const uint32_t sbase = smem_u32(smw);

    const int tid  = threadIdx.x;
    const int warp = tid >> 5, lane = tid & 31;
    const int wm = (warp & 3) * 32;
    const int wn = (warp >> 2) * 64;
    const int r  = lane >> 2, c = lane & 3;
    const int bm  = blockIdx.x * 128;
    const int bn0 = blockIdx.y * 128;

    // ldmatrix per-lane row selectors
    const int a_lrow = lane & 15;           // row within 16-row A frag
    const int a_koff = (lane >> 4) * 4;     // word offset: k-half select
    const int b_lrow = lane & 7;            // row within 8-col B block
    const int b_koff = ((lane >> 3) & 1) * 4;
    const int b_nblk = (lane >> 4) * 8;     // u vs u+1 select

    float acc[2][8][4];
    #pragma unroll
    for (int t = 0; t < 2; t++)
        #pragma unroll
        for (int u = 0; u < 8; u++)
            #pragma unroll
            for (int i = 0; i < 4; i++) acc[t][u][i] = 0.f;

    auto load_tile = [&](int kt, int buf) {
        const int kcol = kt * 32;
        #pragma unroll
        for (int i = 0; i < 8; i++) {
            const int region = i >> 1;
            const int rem = (i & 1) * 256 + tid;
            const int row = rem >> 2;
            const int c16 = tid & 3;
            uint32_t dst = sbase +
                ((uint32_t)((buf * 4 + region) * TILE_WORDS + row * LDW + c16 * 4)) * 4;
            const uint16_t* src;
            int nb = 16;
            if (region < 2) {
                const int grow = bm + row;
                const int rowok = (grow < M) ? grow : 0;
                nb = (grow < M) ? 16 : 0;
                src = (region == 0 ? Ah : Al) + (size_t)rowok * 256 + kcol + c16 * 8;
            } else {
                src = (region == 2 ? Wh : Wl) + (size_t)(bn0 + row) * 256 + kcol + c16 * 8;
            }
            cp16(dst, src, nb);
        }
    };

    load_tile(0, 0);
    asm volatile("cp.async.commit_group;" ::: "memory");
    load_tile(1, 1);
    asm volatile("cp.async.commit_group;" ::: "memory");

    #pragma unroll 1
    for (int kt = 0; kt < 8; kt++) {
        asm volatile("cp.async.wait_group 1;" ::: "memory");
        __syncthreads();

        const int buf = kt & 1;
        const uint32_t abh = sbase + ((buf * 4 + 0) * TILE_WORDS) * 4;
        const uint32_t abl = sbase + ((buf * 4 + 1) * TILE_WORDS) * 4;
        const uint32_t bbh = sbase + ((buf * 4 + 2) * TILE_WORDS) * 4;
        const uint32_t bbl = sbase + ((buf * 4 + 3) * TILE_WORDS) * 4;

        #pragma unroll
        for (int ks = 0; ks < 2; ks++) {
            const int kk = ks * 8;
            uint32_t afh[2][4], afl[2][4], bfh[8][2], bfl[8][2];
            #pragma unroll
            for (int t = 0; t < 2; t++) {
                const uint32_t ar =
                    ((uint32_t)((wm + t * 16 + a_lrow) * LDW + kk + a_koff)) * 4;
                LDSM_X4(afh[t][0], afh[t][1], afh[t][2], afh[t][3], abh + ar);
                LDSM_X4(afl[t][0], afl[t][1], afl[t][2], afl[t][3], abl + ar);
            }
            #pragma unroll
            for (int u = 0; u < 8; u += 2) {
                const uint32_t br =
                    ((uint32_t)((wn + u * 8 + b_nblk + b_lrow) * LDW + kk + b_koff)) * 4;
                LDSM_X4(bfh[u][0], bfh[u][1], bfh[u + 1][0], bfh[u + 1][1], bbh + br);
                LDSM_X4(bfl[u][0], bfl[u][1], bfl[u + 1][0], bfl[u + 1][1], bbl + br);
            }
            #pragma unroll
            for (int t = 0; t < 2; t++)
                #pragma unroll
                for (int u = 0; u < 8; u++) {
                    mma_bf16(acc[t][u], afl[t], bfh[u]);
                    mma_bf16(acc[t][u], afh[t], bfl[u]);
                    mma_bf16(acc[t][u], afh[t], bfh[u]);
                }
        }
        __syncthreads();
        if (kt + 2 < 8) load_tile(kt + 2, buf);
        asm volatile("cp.async.commit_group;" ::: "memory");
    }

    #pragma unroll
    for (int t = 0; t < 2; t++) {
        const int row0 = bm + wm + t * 16 + r;
        #pragma unroll
        for (int u = 0; u < 8; u++) {
            const int col = bn0 + wn + u * 8 + 2 * c;
            if (row0 < M)
                *(float2*)(C + (size_t)row0 * NC + col) =
                    make_float2(acc[t][u][0], acc[t][u][1]);
            if (row0 + 8 < M)
                *(float2*)(C + (size_t)(row0 + 8) * NC + col) =
                    make_float2(acc[t][u][2], acc[t][u][3]);
        }
    }
}

// ---------------- split x into bf16 hi/lo -----------------------------------
__global__ void k_splitx(Ptr4 xs) {
    const int view = blockIdx.y;
    const int i = blockIdx.x * blockDim.x + threadIdx.x;
    if (i >= NN * FIN / 4) return;
    float4 v = ((const float4*)xs.p[view])[i];
    uint32_t h0 = pack_bf16(v.x, v.y);
    uint32_t h1 = pack_bf16(v.z, v.w);
    uint32_t l0 = pack_bf16(v.x - bfLO(h0), v.y - bfHI(h0));
    uint32_t l1 = pack_bf16(v.z - bfLO(h1), v.w - bfHI(h1));
    g_xh[view][i] = make_uint2(h0, h1);
    g_xl[view][i] = make_uint2(l0, l1);
}

// ---------------- batched weight transpose + split ---------------------------
struct TPars {
    const float* src[10];
    int K[10], N[10], dstOff[10];
};
__global__ void k_transpose_all(TPars p) {
    const int m = blockIdx.y;
    const int K = p.K[m], Ncols = p.N[m];
    const float* src = p.src[m];
    uint16_t* dh = g_wth + p.dstOff[m];
    uint16_t* dl = g_wtl + p.dstOff[m];
    const int tot = K * Ncols;
    for (int i = blockIdx.x * blockDim.x + threadIdx.x; i < tot;
         i += gridDim.x * blockDim.x) {
        int k = i / Ncols, n = i % Ncols;
        float v = src[i];
        __nv_bfloat16 hb = __float2bfloat16(v);
        float hf = __bfloat162float(hb);
        __nv_bfloat16 lb = __float2bfloat16(v - hf);
        dh[n * K + k] = *(uint16_t*)&hb;
        dl[n * K + k] = *(uint16_t*)&lb;
    }
}

// ---------------- edge dtype sniff -----------------------------------------
__global__ void k_detect(const int* e32) {
    __shared__ int nz;
    if (threadIdx.x == 0) nz = 0;
    __syncthreads();
    for (int i = threadIdx.x; i < 2048; i += blockDim.x) {
        if (e32[2 * i + 1] != 0) nz = 1;
    }
    __syncthreads();
    if (threadIdx.x == 0) g_fmt64 = (nz == 0) ? 1 : 0;
}

__device__ __forceinline__ int edge_at(const void* e, int idx) {
    if (g_fmt64) return (int)((const long long*)e)[idx];
    return ((const int*)e)[idx];
}

// ---------------- CSR build (2 views per launch, vbase selects group) -------
struct EPtr4 { const void* e[4]; };

__global__ void k_zero_counts(int vbase) {
    int i = blockIdx.x * blockDim.x + threadIdx.x;
    if (i < NN) g_counts[vbase + blockIdx.y][i] = 0;
}

__global__ void k_count(EPtr4 ep, int vbase) {
    int i = blockIdx.x * blockDim.x + threadIdx.x;
    if (i >= EE) return;
    const int v = vbase + blockIdx.y;
    int d = edge_at(ep.e[v], EE + i);
    atomicAdd(&g_counts[v][d], 1);
}

__global__ void k_deg(int vbase) {
    int i = blockIdx.x * blockDim.x + threadIdx.x;
    if (i < NN) {
        int v = vbase + blockIdx.y;
        float dg = (float)(g_counts[v][i] + 1);
        g_dinv[v][i]   = rsqrtf(dg);
        g_deginv[v][i] = 1.0f / dg;
    }
}

__global__ void k_scan(int vbase) {
    const int v = vbase + blockIdx.x;
    __shared__ int sh[1024];
    __shared__ int carry;
    if (threadIdx.x == 0) { carry = 0; g_rowptr[v][0] = 0; }
    __syncthreads();
    for (int base = 0; base < NN; base += 1024) {
        int i = base + threadIdx.x;
        int val = (i < NN) ? g_counts[v][i] : 0;
        sh[threadIdx.x] = val;
        __syncthreads();
        for (int d = 1; d < 1024; d <<= 1) {
            int t = (threadIdx.x >= d) ? sh[threadIdx.x - d] : 0;
            __syncthreads();
            sh[threadIdx.x] += t;
            __syncthreads();
        }
        if (i < NN) {
            g_rowptr[v][i + 1] = carry + sh[threadIdx.x];
            g_cursor[v][i] = 0;
        }
        __syncthreads();
        if (threadIdx.x == 0) carry += sh[1023];
        __syncthreads();
    }
}

__global__ void k_fill(EPtr4 ep, int vbase) {
    int i = blockIdx.x * blockDim.x + threadIdx.x;
    if (i >= EE) return;
    const int v = vbase + blockIdx.y;
    int s = edge_at(ep.e[v], i);
    int d = edge_at(ep.e[v], EE + i);
    int pos = g_rowptr[v][d] + atomicAdd(&g_cursor[v][d], 1);
    g_col[v][pos]  = s;
    g_coef[v][pos] = g_dinv[v][s] * g_dinv[v][d];
}

// ---------------- GCN aggregation + self loop + bias + LeakyReLU ------------
template <int F, bool SPLIT>
__global__ void __launch_bounds__(256)
k_agg(const float* __restrict__ xwAll, Ptr4 bias, float* __restrict__ outAll,
      int vbase) {
    constexpr int TPR = F / 4;
    constexpr int RPB = 256 / TPR;
    const int view = vbase + blockIdx.y;
    const int rid = threadIdx.x / TPR;
    const int f4  = threadIdx.x % TPR;
    const int row = blockIdx.x * RPB + rid;
    if (row >= NN) return;

    const float* __restrict__ xw = xwAll + (size_t)view * NN * F;
    const int* __restrict__ rp   = g_rowptr[view];
    const int* __restrict__ col  = g_col[view];
    const float* __restrict__ cf = g_coef[view];

    const int start = rp[row];
    const int end   = rp[row + 1];
    float4 acc = make_float4(0.f, 0.f, 0.f, 0.f);
    #pragma unroll 2
    for (int p = start; p < end; p++) {
        const int s    = col[p];
        const float w  = cf[p];
        float4 v = *(const float4*)(xw + (size_t)s * F + f4 * 4);
        acc.x += v.x * w; acc.y += v.y * w;
        acc.z += v.z * w; acc.w += v.w * w;
    }
    const float di = g_deginv[view][row];
    float4 sv = *(const float4*)(xw + (size_t)row * F + f4 * 4);
    float4 bv = *(const float4*)(bias.p[view] + f4 * 4);
    float4 o;
    o.x = acc.x + sv.x * di + bv.x;
    o.y = acc.y + sv.y * di + bv.y;
    o.z = acc.z + sv.z * di + bv.z;
    o.w = acc.w + sv.w * di + bv.w;
    o.x = (o.x >= 0.f) ? o.x : 0.2f * o.x;
    o.y = (o.y >= 0.f) ? o.y : 0.2f * o.y;
    o.z = (o.z >= 0.f) ? o.z : 0.2f * o.z;
    o.w = (o.w >= 0.f) ? o.w : 0.2f * o.w;

    if (SPLIT) {
        uint32_t h0 = pack_bf16(o.x, o.y);
        uint32_t h1 = pack_bf16(o.z, o.w);
        uint32_t l0 = pack_bf16(o.x - bfLO(h0), o.y - bfHI(h0));
        uint32_t l1 = pack_bf16(o.z - bfLO(h1), o.w - bfHI(h1));
        const size_t idx = (size_t)row * (F / 4) + f4;
        g_bh[view][idx] = make_uint2(h0, h1);
        g_bl[view][idx] = make_uint2(l0, l1);
    } else {
        float* __restrict__ out = outAll + (size_t)view * NN * F;
        *(float4*)(out + (size_t)row * F + f4 * 4) = o;
    }
}

// ---------------- final combine (batched over 2 node types) ----------------
struct CArgs { const float* res[2]; const float* rb[2]; };
__global__ void k_combine(const float* __restrict__ outSecs,
                          CArgs ca, float* __restrict__ dst) {
    const int j = blockIdx.y;
    const size_t SEC = (size_t)NN * FOUT;
    const float* jv  = outSecs + (2 + j) * SEC;
    const float* bv  = outSecs + (4 + j) * SEC;
    const float* res = ca.res[j];
    int i = blockIdx.x * blockDim.x + threadIdx.x;
    if (i < NN * FOUT) {
        dst[j * SEC + i] = 0.5f * (jv[i] + bv[i]) + res[i]
                         + ca.rb[j][i & (FOUT - 1)];
    }
}

// ---------------- host orchestration ----------------------------------------
#define GEMM_GRID_X ((NN + 127) / 128)

extern "C" void kernel_launch(void* const* d_in, const int* in_sizes, int n_in,
                              void* d_out, int out_size) {
    const float* x_lj = (const float*)d_in[0];
    const float* x_pj = (const float*)d_in[1];
    const float* x_lb = (const float*)d_in[2];
    const float* x_pb = (const float*)d_in[3];

    EPtr4 ep; ep.e[0] = d_in[4]; ep.e[1] = d_in[5]; ep.e[2] = d_in[6]; ep.e[3] = d_in[7];

    const float* W_j1_l = (const float*)d_in[8];   const float* b_j1_l = (const float*)d_in[9];
    const float* W_j1_p = (const float*)d_in[10];  const float* b_j1_p = (const float*)d_in[11];
    const float* W_j2_l = (const float*)d_in[12];  const float* b_j2_l = (const float*)d_in[13];
    const float* W_j2_p = (const float*)d_in[14];  const float* b_j2_p = (const float*)d_in[15];
    const float* W_b1_l = (const float*)d_in[16];  const float* b_b1_l = (const float*)d_in[17];
    const float* W_b1_p = (const float*)d_in[18];  const float* b_b1_p = (const float*)d_in[19];
    const float* W_b2_l = (const float*)d_in[20];  const float* b_b2_l = (const float*)d_in[21];
    const float* W_b2_p = (const float*)d_in[22];  const float* b_b2_p = (const float*)d_in[23];
    const float* W_r_l  = (const float*)d_in[24];  const float* b_r_l  = (const float*)d_in[25];
    const float* W_r_p  = (const float*)d_in[26];  const float* b_r_p  = (const float*)d_in[27];

    float* out = (float*)d_out;
    const size_t SEC = (size_t)NN * FOUT;

    float *bufA, *bufC;
    uint16_t *xh, *xl, *bh, *bl, *wth, *wtl;
    cudaGetSymbolAddress((void**)&bufA, g_bufA);
    cudaGetSymbolAddress((void**)&bufC, g_bufC);
    cudaGetSymbolAddress((void**)&xh,   g_xh);
    cudaGetSymbolAddress((void**)&xl,   g_xl);
    cudaGetSymbolAddress((void**)&bh,   g_bh);
    cudaGetSymbolAddress((void**)&bl,   g_bl);
    cudaGetSymbolAddress((void**)&wth,  g_wth);
    cudaGetSymbolAddress((void**)&wtl,  g_wtl);

    cudaFuncSetAttribute(k_gemm<256>, cudaFuncAttributeMaxDynamicSharedMemorySize, SMEM_GEMM);
    cudaFuncSetAttribute(k_gemm<128>, cudaFuncAttributeMaxDynamicSharedMemorySize, SMEM_GEMM);

    // fresh stream/events per call (never destroyed; replays use the graph)
    cudaStream_t sB;
    cudaEvent_t eF, eX, eB;
    cudaStreamCreateWithFlags(&sB, cudaStreamNonBlocking);
    cudaEventCreateWithFlags(&eF, cudaEventDisableTiming);
    cudaEventCreateWithFlags(&eX, cudaEventDisableTiming);
    cudaEventCreateWithFlags(&eB, cudaEventDisableTiming);

    const size_t NHID = (size_t)NN * HID;
    const size_t NFIN = (size_t)NN * FIN;
    const size_t NOUT = (size_t)NN * FOUT;
    dim3 gz2((NN + 255) / 256, 2);
    dim3 ge2((EE + 255) / 256, 2);

    // ---- legacy: edge dtype, then fork pipeline B -----------------------
    k_detect<<<1, 256>>>((const int*)ep.e[0]);
    cudaEventRecord(eF, 0);
    cudaStreamWaitEvent(sB, eF, 0);

    // ---- pipeline B (stream sB): CSR for views 2,3 ----------------------
    k_zero_counts<<<gz2, 256, 0, sB>>>(2);
    k_count<<<ge2, 256, 0, sB>>>(ep, 2);
    k_deg<<<gz2, 256, 0, sB>>>(2);
    k_scan<<<2, 1024, 0, sB>>>(2);
    k_fill<<<ge2, 256, 0, sB>>>(ep, 2);

    // ---- legacy (pipeline A): prep shared data ---------------------------
    Ptr4 ax; ax.p[0] = x_lj; ax.p[1] = x_pj; ax.p[2] = x_lb; ax.p[3] = x_pb;
    k_splitx<<<dim3((NN * FIN / 4 + 255) / 256, 4), 256>>>(ax);

    TPars tp;
    const float* ws[10] = {W_j1_l, W_j1_p, W_b1_l, W_b1_p,
                           W_j2_l, W_j2_p, W_b2_l, W_b2_p, W_r_l, W_r_p};
    for (int m = 0; m < 10; m++) {
        tp.src[m] = ws[m];
        tp.K[m] = 256;
        tp.N[m] = (m < 4) ? 256 : 128;
        tp.dstOff[m] = (m < 4) ? m * 65536 : 4 * 65536 + (m - 4) * 32768;
    }
    k_transpose_all<<<dim3(64, 10), 256>>>(tp);
    cudaEventRecord(eX, 0);
    cudaStreamWaitEvent(sB, eX, 0);      // B needs splitx + weights

    // ---- pipeline A: CSR for views 0,1 -----------------------------------
    k_zero_counts<<<gz2, 256>>>(0);
    k_count<<<ge2, 256>>>(ep, 0);
    k_deg<<<gz2, 256>>>(0);
    k_scan<<<2, 1024>>>(0);
    k_fill<<<ge2, 256>>>(ep, 0);

    const uint16_t* w2base_h = wth + 4 * 65536;
    const uint16_t* w2base_l = wtl + 4 * 65536;

    // ---- pipeline B compute (views 2,3 + residual_p) ----------------------
    {
        GArgs g1;
        for (int j = 0; j < 2; j++) {
            int v = 2 + j;
            g1.ah[j] = xh + (size_t)v * NFIN;  g1.al[j] = xl + (size_t)v * NFIN;
            g1.wh[j] = wth + v * 65536;        g1.wl[j] = wtl + v * 65536;
            g1.c[j]  = bufA + (size_t)v * NHID;
        }
        g1.ah[2] = g1.ah[0]; g1.al[2] = g1.al[0];
        g1.wh[2] = g1.wh[0]; g1.wl[2] = g1.wl[0]; g1.c[2] = g1.c[0];
        k_gemm<256><<<dim3(GEMM_GRID_X, 2, 2), 256, SMEM_GEMM, sB>>>(g1, NN);

        Ptr4 b1; b1.p[0] = b_j1_l; b1.p[1] = b_j1_p; b1.p[2] = b_b1_l; b1.p[3] = b_b1_p;
        k_agg<HID, true><<<dim3((NN + 3) / 4, 2), 256, 0, sB>>>(bufA, b1, nullptr, 2);

        GArgs g2;
        for (int j = 0; j < 2; j++) {
            int v = 2 + j;
            g2.ah[j] = bh + (size_t)v * NHID;  g2.al[j] = bl + (size_t)v * NHID;
            g2.wh[j] = w2base_h + v * 32768;   g2.wl[j] = w2base_l + v * 32768;
            g2.c[j]  = bufC + (size_t)v * NOUT;
        }
        // residual_p: A = x_pj (view 1 split), W = W_r_p (slot 5); out -> bufA[2]
        g2.ah[2] = xh + 1 * NFIN;  g2.al[2] = xl + 1 * NFIN;
        g2.wh[2] = w2base_h + 5 * 32768;  g2.wl[2] = w2base_l + 5 * 32768;
        g2.c[2]  = bufA + 2 * NHID;
        k_gemm<128><<<dim3(GEMM_GRID_X, 1, 3), 256, SMEM_GEMM, sB>>>(g2, NN);

        Ptr4 b2; b2.p[0] = b_j2_l; b2.p[1] = b_j2_p; b2.p[2] = b_b2_l; b2.p[3] = b_b2_p;
        k_agg<FOUT, false><<<dim3((NN + 7) / 8, 2), 256, 0, sB>>>(
            bufC, b2, out + 2 * SEC, 2);
        cudaEventRecord(eB, sB);
    }

    // ---- pipeline A compute (views 0,1 + residual_l) ----------------------
    {
        GArgs g1;
        for (int j = 0; j < 2; j++) {
            g1.ah[j] = xh + (size_t)j * NFIN;  g1.al[j] = xl + (size_t)j * NFIN;
            g1.wh[j] = wth + j * 65536;        g1.wl[j] = wtl + j * 65536;
            g1.c[j]  = bufA + (size_t)j * NHID;
        }
        g1.ah[2] = g1.ah[0]; g1.al[2] = g1.al[0];
        g1.wh[2] = g1.wh[0]; g1.wl[2] = g1.wl[0]; g1.c[2] = g1.c[0];
        k_gemm<256><<<dim3(GEMM_GRID_X, 2, 2), 256, SMEM_GEMM>>>(g1, NN);

        Ptr4 b1; b1.p[0] = b_j1_l; b1.p[1] = b_j1_p; b1.p[2] = b_b1_l; b1.p[3] = b_b1_p;
        k_agg<HID, true><<<dim3((NN + 3) / 4, 2), 256>>>(bufA, b1, nullptr, 0);

        GArgs g2;
        for (int j = 0; j < 2; j++) {
            g2.ah[j] = bh + (size_t)j * NHID;  g2.al[j] = bl + (size_t)j * NHID;
            g2.wh[j] = w2base_h + j * 32768;   g2.wl[j] = w2base_l + j * 32768;
            g2.c[j]  = bufC + (size_t)j * NOUT;
        }
        // residual_l: A = x_lj (view 0 split), W = W_r_l (slot 4); out -> bufA[0]
        g2.ah[2] = xh;  g2.al[2] = xl;
        g2.wh[2] = w2base_h + 4 * 32768;  g2.wl[2] = w2base_l + 4 * 32768;
        g2.c[2]  = bufA;
        k_gemm<128><<<dim3(GEMM_GRID_X, 1, 3), 256, SMEM_GEMM>>>(g2, NN);

        Ptr4 b2; b2.p[0] = b_j2_l; b2.p[1] = b_j2_p; b2.p[2] = b_b2_l; b2.p[3] = b_b2_p;
        k_agg<FOUT, false><<<dim3((NN + 7) / 8, 2), 256>>>(
            bufC, b2, out + 2 * SEC, 0);
    }

    // ---- join and combine -------------------------------------------------
    cudaStreamWaitEvent(0, eB, 0);
    CArgs ca;
    ca.res[0] = bufA;                 // residual_l
    ca.res[1] = bufA + 2 * NHID;      // residual_p
    ca.rb[0] = b_r_l; ca.rb[1] = b_r_p;
    k_combine<<<dim3((NN * FOUT + 255) / 256, 2), 256>>>(out, ca, out);
}

// round 10
// speedup vs baseline: 1.0411x; 1.0411x over previous
#include <cuda_runtime.h>
#include <cuda_bf16.h>
#include <cstdint>
#include <math.h>

#define NN   50000
#define EE   800000
#define FIN  256
#define HID  256
#define FOUT 128

// ---------------- scratch (device globals; no allocation allowed) ----------
__device__ float g_bufA[4][NN * HID];   // gemm1 out; [0],[2] reused for residual out
__device__ float g_bufB[4][NN * HID];   // hidden after agg1
__device__ float g_bufC[4][NN * FOUT];  // gemm2 out
__device__ float g_wt[4 * 65536 + 6 * 32768];  // transposed fp32 weights
__device__ float g_dinv[4][NN];
__device__ float g_deginv[4][NN];
__device__ int   g_counts[4][NN];
__device__ int   g_cursor[4][NN];
__device__ int   g_rowptr[4][NN + 1];
__device__ int   g_col[4][EE];
__device__ float g_coef[4][EE];
__device__ int   g_fmt64;

struct Ptr4 { const float* p[4]; };

// ==================== helpers ================================================
__device__ __forceinline__ void cp16(uint32_t dst, const void* src, int nbytes) {
    asm volatile("cp.async.cg.shared.global [%0], [%1], 16, %2;"
                 :: "r"(dst), "l"(src), "r"(nbytes));
}

__device__ __forceinline__ void mma_bf16(float* d, const uint32_t* a, const uint32_t* b) {
    asm volatile(
        "mma.sync.aligned.m16n8k16.row.col.f32.bf16.bf16.f32 "
        "{%0,%1,%2,%3}, {%4,%5,%6,%7}, {%8,%9}, {%0,%1,%2,%3};"
        : "+f"(d[0]), "+f"(d[1]), "+f"(d[2]), "+f"(d[3])
        : "r"(a[0]), "r"(a[1]), "r"(a[2]), "r"(a[3]), "r"(b[0]), "r"(b[1]));
}

__device__ __forceinline__ uint32_t pack_bf16(float x, float y) {
    uint32_t r;
    asm("cvt.rn.bf16x2.f32 %0, %1, %2;" : "=r"(r) : "f"(y), "f"(x));
    return r;
}

// split float2 into bf16x2 hi + bf16x2 lo (residual)
__device__ __forceinline__ void split2(float2 v, uint32_t& hi, uint32_t& lo) {
    hi = pack_bf16(v.x, v.y);
    float h0 = __uint_as_float(hi << 16);
    float h1 = __uint_as_float(hi & 0xffff0000u);
    lo = pack_bf16(v.x - h0, v.y - h1);
}

__device__ __forceinline__ uint32_t smem_u32(const void* p) {
    uint32_t a;
    asm("{ .reg .u64 t; cvta.to.shared.u64 t, %1; cvt.u32.u64 %0, t; }"
        : "=r"(a) : "l"(p));
    return a;
}

// ==================== fused-split 3xBF16 GEMM (round-6 proven) ==============
// C[M,NC] = A[M,256] @ Wt^T, A/Wt fp32, split to bf16 hi/lo in-register.
#define LDSA 40
#define BUF_FLOATS (128 * LDSA)
#define SMEM_GEMM (4 * BUF_FLOATS * 4)   // 81920 B

struct GArgs { const float *a[3], *w[3]; float* c[3]; };

template<int NC>
__global__ void __launch_bounds__(256, 1)
k_gemm(GArgs g, int M)
{
    const int z = blockIdx.z;
    const float* __restrict__ A  = g.a[z];
    const float* __restrict__ Bt = g.w[z];
    float* __restrict__ C        = g.c[z];

    extern __shared__ float sm[];
    float* As = sm;
    float* Bs = sm + 2 * BUF_FLOATS;
    const uint32_t sA = smem_u32(As);
    const uint32_t sB = smem_u32(Bs);

    const int tid  = threadIdx.x;
    const int warp = tid >> 5, lane = tid & 31;
    const int wm = (warp & 3) * 32;
    const int wn = (warp >> 2) * 64;
    const int r  = lane >> 2, c = lane & 3;
    const int bm  = blockIdx.x * 128;
    const int bn0 = blockIdx.y * 128;

    const int lr0 = tid >> 3;
    const int lc4 = tid & 7;

    float acc[2][8][4];
    #pragma unroll
    for (int t = 0; t < 2; t++)
        #pragma unroll
        for (int u = 0; u < 8; u++)
            #pragma unroll
            for (int i = 0; i < 4; i++) acc[t][u][i] = 0.f;

    auto load_tile = [&](int kt, int buf) {
        const int k0 = kt * 32;
        #pragma unroll
        for (int i = 0; i < 4; i++) {
            const int row = lr0 + i * 32;
            const uint32_t soff = (uint32_t)((row * LDSA + lc4 * 4) * 4);
            const int grow = bm + row;
            const int rowok = (grow < M) ? grow : 0;
            cp16(sA + buf * (BUF_FLOATS * 4) + soff,
                 A + (size_t)rowok * 256 + k0 + lc4 * 4,
                 (grow < M) ? 16 : 0);
            cp16(sB + buf * (BUF_FLOATS * 4) + soff,
                 Bt + (size_t)(bn0 + row) * 256 + k0 + lc4 * 4, 16);
        }
    };

    load_tile(0, 0);
    asm volatile("cp.async.commit_group;" ::: "memory");
    load_tile(1, 1);
    asm volatile("cp.async.commit_group;" ::: "memory");

    #pragma unroll 1
    for (int kt = 0; kt < 8; kt++) {
        asm volatile("cp.async.wait_group 1;" ::: "memory");
        __syncthreads();

        const int buf = kt & 1;
        const float* Ab = As + buf * BUF_FLOATS;
        const float* Bb = Bs + buf * BUF_FLOATS;
        #pragma unroll
        for (int ks = 0; ks < 2; ks++) {
            const int kk = ks * 16;
            uint32_t afh[2][4], afl[2][4], bfh[8][2], bfl[8][2];
            #pragma unroll
            for (int t = 0; t < 2; t++) {
                const float* ap = Ab + (wm + t * 16 + r) * LDSA + kk + 2 * c;
                split2(*(const float2*)(ap),                afh[t][0], afl[t][0]);
                split2(*(const float2*)(ap + 8 * LDSA),     afh[t][1], afl[t][1]);
                split2(*(const float2*)(ap + 8),            afh[t][2], afl[t][2]);
                split2(*(const float2*)(ap + 8 * LDSA + 8), afh[t][3], afl[t][3]);
            }
            #pragma unroll
            for (int u = 0; u < 8; u++) {
                const float* bp = Bb + (wn + u * 8 + r) * LDSA + kk + 2 * c;
                split2(*(const float2*)(bp),     bfh[u][0], bfl[u][0]);
                split2(*(const float2*)(bp + 8), bfh[u][1], bfl[u][1]);
            }
            #pragma unroll
            for (int t = 0; t < 2; t++)
                #pragma unroll
                for (int u = 0; u < 8; u++) {
                    mma_bf16(acc[t][u], afl[t], bfh[u]);
                    mma_bf16(acc[t][u], afh[t], bfl[u]);
                    mma_bf16(acc[t][u], afh[t], bfh[u]);
                }
        }
        __syncthreads();
        if (kt + 2 < 8) load_tile(kt + 2, buf);
        asm volatile("cp.async.commit_group;" ::: "memory");
    }

    #pragma unroll
    for (int t = 0; t < 2; t++) {
        const int row0 = bm + wm + t * 16 + r;
        #pragma unroll
        for (int u = 0; u < 8; u++) {
            const int col = bn0 + wn + u * 8 + 2 * c;
            if (row0 < M)
                *(float2*)(C + (size_t)row0 * NC + col) =
                    make_float2(acc[t][u][0], acc[t][u][1]);
            if (row0 + 8 < M)
                *(float2*)(C + (size_t)(row0 + 8) * NC + col) =
                    make_float2(acc[t][u][2], acc[t][u][3]);
        }
    }
}

// ---------------- batched weight transpose (fp32) ---------------------------
struct TPars {
    const float* src[10];
    int K[10], N[10], dstOff[10];
};
__global__ void k_transpose_all(TPars p) {
    const int m = blockIdx.y;
    const int K = p.K[m], Ncols = p.N[m];
    const float* src = p.src[m];
    float* dst = g_wt + p.dstOff[m];
    const int tot = K * Ncols;
    for (int i = blockIdx.x * blockDim.x + threadIdx.x; i < tot;
         i += gridDim.x * blockDim.x) {
        int k = i / Ncols, n = i % Ncols;
        dst[n * K + k] = src[i];
    }
}

// ---------------- edge dtype sniff -----------------------------------------
__global__ void k_detect(const int* e32) {
    __shared__ int nz;
    if (threadIdx.x == 0) nz = 0;
    __syncthreads();
    for (int i = threadIdx.x; i < 2048; i += blockDim.x) {
        if (e32[2 * i + 1] != 0) nz = 1;
    }
    __syncthreads();
    if (threadIdx.x == 0) g_fmt64 = (nz == 0) ? 1 : 0;
}

__device__ __forceinline__ int edge_at(const void* e, int idx) {
    if (g_fmt64) return (int)((const long long*)e)[idx];
    return ((const int*)e)[idx];
}

// ---------------- CSR build (2 views per launch) ----------------------------
struct EPtr4 { const void* e[4]; };

__global__ void k_zero_counts(int vbase) {
    int i = blockIdx.x * blockDim.x + threadIdx.x;
    if (i < NN) g_counts[vbase + blockIdx.y][i] = 0;
}

__global__ void k_count(EPtr4 ep, int vbase) {
    int i = blockIdx.x * blockDim.x + threadIdx.x;
    if (i >= EE) return;
    const int v = vbase + blockIdx.y;
    int d = edge_at(ep.e[v], EE + i);
    atomicAdd(&g_counts[v][d], 1);
}

__global__ void k_deg(int vbase) {
    int i = blockIdx.x * blockDim.x + threadIdx.x;
    if (i < NN) {
        int v = vbase + blockIdx.y;
        float dg = (float)(g_counts[v][i] + 1);
        g_dinv[v][i]   = rsqrtf(dg);
        g_deginv[v][i] = 1.0f / dg;
    }
}

__global__ void k_scan(int vbase) {
    const int v = vbase + blockIdx.x;
    __shared__ int sh[1024];
    __shared__ int carry;
    if (threadIdx.x == 0) { carry = 0; g_rowptr[v][0] = 0; }
    __syncthreads();
    for (int base = 0; base < NN; base += 1024) {
        int i = base + threadIdx.x;
        int val = (i < NN) ? g_counts[v][i] : 0;
        sh[threadIdx.x] = val;
        __syncthreads();
        for (int d = 1; d < 1024; d <<= 1) {
            int t = (threadIdx.x >= d) ? sh[threadIdx.x - d] : 0;
            __syncthreads();
            sh[threadIdx.x] += t;
            __syncthreads();
        }
        if (i < NN) {
            g_rowptr[v][i + 1] = carry + sh[threadIdx.x];
            g_cursor[v][i] = 0;
        }
        __syncthreads();
        if (threadIdx.x == 0) carry += sh[1023];
        __syncthreads();
    }
}

__global__ void k_fill(EPtr4 ep, int vbase) {
    int i = blockIdx.x * blockDim.x + threadIdx.x;
    if (i >= EE) return;
    const int v = vbase + blockIdx.y;
    int s = edge_at(ep.e[v], i);
    int d = edge_at(ep.e[v], EE + i);
    int pos = g_rowptr[v][d] + atomicAdd(&g_cursor[v][d], 1);
    g_col[v][pos]  = s;
    g_coef[v][pos] = g_dinv[v][s] * g_dinv[v][d];
}

// ---------------- GCN aggregation + self loop + bias + LeakyReLU ------------
template <int F>
__global__ void __launch_bounds__(256)
k_agg(const float* __restrict__ xwAll, Ptr4 bias, float* __restrict__ outAll,
      int vbase) {
    constexpr int TPR = F / 4;
    constexpr int RPB = 256 / TPR;
    const int view = vbase + blockIdx.y;
    const int rid = threadIdx.x / TPR;
    const int f4  = threadIdx.x % TPR;
    const int row = blockIdx.x * RPB + rid;
    if (row >= NN) return;

    const float* __restrict__ xw = xwAll + (size_t)view * NN * F;
    float* __restrict__ out      = outAll + (size_t)view * NN * F;
    const int* __restrict__ rp   = g_rowptr[view];
    const int* __restrict__ col  = g_col[view];
    const float* __restrict__ cf = g_coef[view];

    const int start = rp[row];
    const int end   = rp[row + 1];
    float4 acc = make_float4(0.f, 0.f, 0.f, 0.f);
    for (int p = start; p < end; p++) {
        const int s    = col[p];
        const float w  = cf[p];
        float4 v = *(const float4*)(xw + (size_t)s * F + f4 * 4);
        acc.x += v.x * w; acc.y += v.y * w;
        acc.z += v.z * w; acc.w += v.w * w;
    }
    const float di = g_deginv[view][row];
    float4 sv = *(const float4*)(xw + (size_t)row * F + f4 * 4);
    float4 bv = *(const float4*)(bias.p[view] + f4 * 4);
    float4 o;
    o.x = acc.x + sv.x * di + bv.x;
    o.y = acc.y + sv.y * di + bv.y;
    o.z = acc.z + sv.z * di + bv.z;
    o.w = acc.w + sv.w * di + bv.w;
    o.x = (o.x >= 0.f) ? o.x : 0.2f * o.x;
    o.y = (o.y >= 0.f) ? o.y : 0.2f * o.y;
    o.z = (o.z >= 0.f) ? o.z : 0.2f * o.z;
    o.w = (o.w >= 0.f) ? o.w : 0.2f * o.w;
    *(float4*)(out + (size_t)row * F + f4 * 4) = o;
}

// ---------------- final combine (batched over 2 node types) ----------------
struct CArgs { const float* res[2]; const float* rb[2]; };
__global__ void k_combine(const float* __restrict__ outSecs,
                          CArgs ca, float* __restrict__ dst) {
    const int j = blockIdx.y;
    const size_t SEC = (size_t)NN * FOUT;
    const float* jv  = outSecs + (2 + j) * SEC;
    const float* bv  = outSecs + (4 + j) * SEC;
    const float* res = ca.res[j];
    int i = blockIdx.x * blockDim.x + threadIdx.x;
    if (i < NN * FOUT) {
        dst[j * SEC + i] = 0.5f * (jv[i] + bv[i]) + res[i]
                         + ca.rb[j][i & (FOUT - 1)];
    }
}

// ---------------- host orchestration ----------------------------------------
#define GEMM_GRID_X ((NN + 127) / 128)

extern "C" void kernel_launch(void* const* d_in, const int* in_sizes, int n_in,
                              void* d_out, int out_size) {
    const float* x_lj = (const float*)d_in[0];
    const float* x_pj = (const float*)d_in[1];
    const float* x_lb = (const float*)d_in[2];
    const float* x_pb = (const float*)d_in[3];

    EPtr4 ep; ep.e[0] = d_in[4]; ep.e[1] = d_in[5]; ep.e[2] = d_in[6]; ep.e[3] = d_in[7];

    const float* W_j1_l = (const float*)d_in[8];   const float* b_j1_l = (const float*)d_in[9];
    const float* W_j1_p = (const float*)d_in[10];  const float* b_j1_p = (const float*)d_in[11];
    const float* W_j2_l = (const float*)d_in[12];  const float* b_j2_l = (const float*)d_in[13];
    const float* W_j2_p = (const float*)d_in[14];  const float* b_j2_p = (const float*)d_in[15];
    const float* W_b1_l = (const float*)d_in[16];  const float* b_b1_l = (const float*)d_in[17];
    const float* W_b1_p = (const float*)d_in[18];  const float* b_b1_p = (const float*)d_in[19];
    const float* W_b2_l = (const float*)d_in[20];  const float* b_b2_l = (const float*)d_in[21];
    const float* W_b2_p = (const float*)d_in[22];  const float* b_b2_p = (const float*)d_in[23];
    const float* W_r_l  = (const float*)d_in[24];  const float* b_r_l  = (const float*)d_in[25];
    const float* W_r_p  = (const float*)d_in[26];  const float* b_r_p  = (const float*)d_in[27];

    float* out = (float*)d_out;
    const size_t SEC = (size_t)NN * FOUT;

    float *bufA, *bufB, *bufC, *wt;
    cudaGetSymbolAddress((void**)&bufA, g_bufA);
    cudaGetSymbolAddress((void**)&bufB, g_bufB);
    cudaGetSymbolAddress((void**)&bufC, g_bufC);
    cudaGetSymbolAddress((void**)&wt,   g_wt);

    cudaFuncSetAttribute(k_gemm<256>, cudaFuncAttributeMaxDynamicSharedMemorySize, SMEM_GEMM);
    cudaFuncSetAttribute(k_gemm<128>, cudaFuncAttributeMaxDynamicSharedMemorySize, SMEM_GEMM);

    // fresh stream/events per call (never destroyed; replays use the graph)
    cudaStream_t sB;
    cudaEvent_t eF, eT, eG1, eB;
    cudaStreamCreateWithFlags(&sB, cudaStreamNonBlocking);
    cudaEventCreateWithFlags(&eF,  cudaEventDisableTiming);
    cudaEventCreateWithFlags(&eT,  cudaEventDisableTiming);
    cudaEventCreateWithFlags(&eG1, cudaEventDisableTiming);
    cudaEventCreateWithFlags(&eB,  cudaEventDisableTiming);

    const size_t NHID = (size_t)NN * HID;
    const size_t NOUT = (size_t)NN * FOUT;
    dim3 gz2((NN + 255) / 256, 2);
    dim3 ge2((EE + 255) / 256, 2);

    const float* w2 = wt + 4 * 65536;

    // ---- stream 0: detect, fork B ----------------------------------------
    k_detect<<<1, 256>>>((const int*)ep.e[0]);
    cudaEventRecord(eF, 0);
    cudaStreamWaitEvent(sB, eF, 0);

    // ---- stream B: CSR for views 2,3 (overlaps A's CSR + transpose) ------
    k_zero_counts<<<gz2, 256, 0, sB>>>(2);
    k_count<<<ge2, 256, 0, sB>>>(ep, 2);
    k_deg<<<gz2, 256, 0, sB>>>(2);
    k_scan<<<2, 1024, 0, sB>>>(2);
    k_fill<<<ge2, 256, 0, sB>>>(ep, 2);

    // ---- stream 0 (pipeline A): weights + CSR(0,1) ------------------------
    TPars tp;
    const float* ws[10] = {W_j1_l, W_j1_p, W_b1_l, W_b1_p,
                           W_j2_l, W_j2_p, W_b2_l, W_b2_p, W_r_l, W_r_p};
    for (int m = 0; m < 10; m++) {
        tp.src[m] = ws[m];
        tp.K[m] = 256;
        tp.N[m] = (m < 4) ? 256 : 128;
        tp.dstOff[m] = (m < 4) ? m * 65536 : 4 * 65536 + (m - 4) * 32768;
    }
    k_transpose_all<<<dim3(64, 10), 256>>>(tp);
    cudaEventRecord(eT, 0);

    k_zero_counts<<<gz2, 256>>>(0);
    k_count<<<ge2, 256>>>(ep, 0);
    k_deg<<<gz2, 256>>>(0);
    k_scan<<<2, 1024>>>(0);
    k_fill<<<ge2, 256>>>(ep, 0);

    // ---- pipeline A: gemm1 (views 0,1) ------------------------------------
    GArgs a1;
    a1.a[0] = x_lj;        a1.w[0] = wt;            a1.c[0] = bufA;
    a1.a[1] = x_pj;        a1.w[1] = wt + 65536;    a1.c[1] = bufA + NHID;
    a1.a[2] = a1.a[0];     a1.w[2] = a1.w[0];       a1.c[2] = a1.c[0];
    k_gemm<256><<<dim3(GEMM_GRID_X, 2, 2), 256, SMEM_GEMM>>>(a1, NN);
    cudaEventRecord(eG1, 0);   // stagger point

    // ---- pipeline B: gemm1 (views 2,3) — starts when A's gemm1 is done ----
    cudaStreamWaitEvent(sB, eT, 0);
    cudaStreamWaitEvent(sB, eG1, 0);
    GArgs b1g;
    b1g.a[0] = x_lb;       b1g.w[0] = wt + 2 * 65536;  b1g.c[0] = bufA + 2 * NHID;
    b1g.a[1] = x_pb;       b1g.w[1] = wt + 3 * 65536;  b1g.c[1] = bufA + 3 * NHID;
    b1g.a[2] = b1g.a[0];   b1g.w[2] = b1g.w[0];        b1g.c[2] = b1g.c[0];
    k_gemm<256><<<dim3(GEMM_GRID_X, 2, 2), 256, SMEM_GEMM, sB>>>(b1g, NN);

    // ---- A: agg1 (overlaps B gemm1) ---------------------------------------
    Ptr4 bb1; bb1.p[0] = b_j1_l; bb1.p[1] = b_j1_p; bb1.p[2] = b_b1_l; bb1.p[3] = b_b1_p;
    k_agg<HID><<<dim3((NN + 3) / 4, 2), 256>>>(bufA, bb1, bufB, 0);

    // ---- B: agg1 (overlaps A gemm2) ---------------------------------------
    k_agg<HID><<<dim3((NN + 3) / 4, 2), 256, 0, sB>>>(bufA, bb1, bufB, 2);

    // ---- A: gemm2 + residual_l (z=3) --------------------------------------
    GArgs a2;
    a2.a[0] = bufB;        a2.w[0] = w2;            a2.c[0] = bufC;
    a2.a[1] = bufB + NHID; a2.w[1] = w2 + 32768;    a2.c[1] = bufC + NOUT;
    a2.a[2] = x_lj;        a2.w[2] = w2 + 4 * 32768; a2.c[2] = bufA;   // res_l
    k_gemm<128><<<dim3(GEMM_GRID_X, 1, 3), 256, SMEM_GEMM>>>(a2, NN);

    // ---- B: gemm2 + residual_p (z=3) --------------------------------------
    GArgs b2g;
    b2g.a[0] = bufB + 2 * NHID; b2g.w[0] = w2 + 2 * 32768; b2g.c[0] = bufC + 2 * NOUT;
    b2g.a[1] = bufB + 3 * NHID; b2g.w[1] = w2 + 3 * 32768; b2g.c[1] = bufC + 3 * NOUT;
    b2g.a[2] = x_pj;            b2g.w[2] = w2 + 5 * 32768; b2g.c[2] = bufA + 2 * NHID; // res_p
    k_gemm<128><<<dim3(GEMM_GRID_X, 1, 3), 256, SMEM_GEMM, sB>>>(b2g, NN);

    // ---- A: agg2 -> out sections 2,3 ---------------------------------------
    Ptr4 bb2; bb2.p[0] = b_j2_l; bb2.p[1] = b_j2_p; bb2.p[2] = b_b2_l; bb2.p[3] = b_b2_p;
    k_agg<FOUT><<<dim3((NN + 7) / 8, 2), 256>>>(bufC, bb2, out + 2 * SEC, 0);

    // ---- B: agg2 -> out sections 4,5 ---------------------------------------
    k_agg<FOUT><<<dim3((NN + 7) / 8, 2), 256, 0, sB>>>(bufC, bb2, out + 2 * SEC, 2);
    cudaEventRecord(eB, sB);

    // ---- join and combine ---------------------------------------------------
    cudaStreamWaitEvent(0, eB, 0);
    CArgs ca;
    ca.res[0] = bufA;                 // residual_l
    ca.res[1] = bufA + 2 * NHID;      // residual_p
    ca.rb[0] = b_r_l; ca.rb[1] = b_r_p;
    k_combine<<<dim3((NN * FOUT + 255) / 256, 2), 256>>>(out, ca, out);
}

// round 11
// speedup vs baseline: 1.1617x; 1.1159x over previous
#include <cuda_runtime.h>
#include <cuda_bf16.h>
#include <cuda_fp16.h>
#include <cstdint>
#include <math.h>

#define NN   50000
#define EE   800000
#define FIN  256
#define HID  256
#define FOUT 128

// ---------------- scratch (device globals; no allocation allowed) ----------
__device__ float  g_bufA[4][NN * HID];   // residual gemm outputs (slots 0,2)
__device__ float  g_bufB[4][NN * HID];   // hidden after agg1 (fp32)
__device__ float  g_bufC[4][NN * FOUT];  // gemm2 out (fp32)
__device__ __half g_xwh[4][NN * HID];    // gemm1 out (fp16) for agg1 gather
__device__ float  g_wt[4 * 65536 + 6 * 32768];  // transposed fp32 weights
__device__ float  g_dinv[4][NN];
__device__ float  g_deginv[4][NN];
__device__ int    g_counts[4][NN];
__device__ int    g_cursor[4][NN];
__device__ int    g_rowptr[4][NN + 1];
__device__ int    g_col[4][EE];
__device__ float  g_coef[4][EE];
__device__ int    g_fmt64;

struct Ptr4 { const float* p[4]; };

// ==================== helpers ================================================
__device__ __forceinline__ void cp16(uint32_t dst, const void* src, int nbytes) {
    asm volatile("cp.async.cg.shared.global [%0], [%1], 16, %2;"
                 :: "r"(dst), "l"(src), "r"(nbytes));
}

__device__ __forceinline__ void mma_bf16(float* d, const uint32_t* a, const uint32_t* b) {
    asm volatile(
        "mma.sync.aligned.m16n8k16.row.col.f32.bf16.bf16.f32 "
        "{%0,%1,%2,%3}, {%4,%5,%6,%7}, {%8,%9}, {%0,%1,%2,%3};"
        : "+f"(d[0]), "+f"(d[1]), "+f"(d[2]), "+f"(d[3])
        : "r"(a[0]), "r"(a[1]), "r"(a[2]), "r"(a[3]), "r"(b[0]), "r"(b[1]));
}

__device__ __forceinline__ uint32_t pack_bf16(float x, float y) {
    uint32_t r;
    asm("cvt.rn.bf16x2.f32 %0, %1, %2;" : "=r"(r) : "f"(y), "f"(x));
    return r;
}

__device__ __forceinline__ void split2(float2 v, uint32_t& hi, uint32_t& lo) {
    hi = pack_bf16(v.x, v.y);
    float h0 = __uint_as_float(hi << 16);
    float h1 = __uint_as_float(hi & 0xffff0000u);
    lo = pack_bf16(v.x - h0, v.y - h1);
}

__device__ __forceinline__ uint32_t smem_u32(const void* p) {
    uint32_t a;
    asm("{ .reg .u64 t; cvta.to.shared.u64 t, %1; cvt.u32.u64 %0, t; }"
        : "=r"(a) : "l"(p));
    return a;
}

// ==================== fused-split 3xBF16 GEMM ===============================
#define LDSA 40
#define BUF_FLOATS (128 * LDSA)
#define SMEM_GEMM (4 * BUF_FLOATS * 4)   // 81920 B

struct GArgs { const float *a[3], *w[3]; void* c[3]; };

template<int NC, bool HOUT>
__global__ void __launch_bounds__(256, 1)
k_gemm(GArgs g, int M)
{
    const int z = blockIdx.z;
    const float* __restrict__ A  = g.a[z];
    const float* __restrict__ Bt = g.w[z];
    void* __restrict__ C         = g.c[z];

    extern __shared__ float sm[];
    float* As = sm;
    float* Bs = sm + 2 * BUF_FLOATS;
    const uint32_t sA = smem_u32(As);
    const uint32_t sB = smem_u32(Bs);

    const int tid  = threadIdx.x;
    const int warp = tid >> 5, lane = tid & 31;
    const int wm = (warp & 3) * 32;
    const int wn = (warp >> 2) * 64;
    const int r  = lane >> 2, c = lane & 3;
    const int bm  = blockIdx.x * 128;
    const int bn0 = blockIdx.y * 128;

    const int lr0 = tid >> 3;
    const int lc4 = tid & 7;

    float acc[2][8][4];
    #pragma unroll
    for (int t = 0; t < 2; t++)
        #pragma unroll
        for (int u = 0; u < 8; u++)
            #pragma unroll
            for (int i = 0; i < 4; i++) acc[t][u][i] = 0.f;

    auto load_tile = [&](int kt, int buf) {
        const int k0 = kt * 32;
        #pragma unroll
        for (int i = 0; i < 4; i++) {
            const int row = lr0 + i * 32;
            const uint32_t soff = (uint32_t)((row * LDSA + lc4 * 4) * 4);
            const int grow = bm + row;
            const int rowok = (grow < M) ? grow : 0;
            cp16(sA + buf * (BUF_FLOATS * 4) + soff,
                 A + (size_t)rowok * 256 + k0 + lc4 * 4,
                 (grow < M) ? 16 : 0);
            cp16(sB + buf * (BUF_FLOATS * 4) + soff,
                 Bt + (size_t)(bn0 + row) * 256 + k0 + lc4 * 4, 16);
        }
    };

    load_tile(0, 0);
    asm volatile("cp.async.commit_group;" ::: "memory");
    load_tile(1, 1);
    asm volatile("cp.async.commit_group;" ::: "memory");

    #pragma unroll 1
    for (int kt = 0; kt < 8; kt++) {
        asm volatile("cp.async.wait_group 1;" ::: "memory");
        __syncthreads();

        const int buf = kt & 1;
        const float* Ab = As + buf * BUF_FLOATS;
        const float* Bb = Bs + buf * BUF_FLOATS;
        #pragma unroll
        for (int ks = 0; ks < 2; ks++) {
            const int kk = ks * 16;
            uint32_t afh[2][4], afl[2][4], bfh[8][2], bfl[8][2];
            #pragma unroll
            for (int t = 0; t < 2; t++) {
                const float* ap = Ab + (wm + t * 16 + r) * LDSA + kk + 2 * c;
                split2(*(const float2*)(ap),                afh[t][0], afl[t][0]);
                split2(*(const float2*)(ap + 8 * LDSA),     afh[t][1], afl[t][1]);
                split2(*(const float2*)(ap + 8),            afh[t][2], afl[t][2]);
                split2(*(const float2*)(ap + 8 * LDSA + 8), afh[t][3], afl[t][3]);
            }
            #pragma unroll
            for (int u = 0; u < 8; u++) {
                const float* bp = Bb + (wn + u * 8 + r) * LDSA + kk + 2 * c;
                split2(*(const float2*)(bp),     bfh[u][0], bfl[u][0]);
                split2(*(const float2*)(bp + 8), bfh[u][1], bfl[u][1]);
            }
            #pragma unroll
            for (int t = 0; t < 2; t++)
                #pragma unroll
                for (int u = 0; u < 8; u++) {
                    mma_bf16(acc[t][u], afl[t], bfh[u]);
                    mma_bf16(acc[t][u], afh[t], bfl[u]);
                    mma_bf16(acc[t][u], afh[t], bfh[u]);
                }
        }
        __syncthreads();
        if (kt + 2 < 8) load_tile(kt + 2, buf);
        asm volatile("cp.async.commit_group;" ::: "memory");
    }

    // ---- epilogue ----
    #pragma unroll
    for (int t = 0; t < 2; t++) {
        const int row0 = bm + wm + t * 16 + r;
        #pragma unroll
        for (int u = 0; u < 8; u++) {
            const int col = bn0 + wn + u * 8 + 2 * c;
            if (HOUT) {
                __half* Ch = (__half*)C;
                if (row0 < M)
                    *(__half2*)(Ch + (size_t)row0 * NC + col) =
                        __floats2half2_rn(acc[t][u][0], acc[t][u][1]);
                if (row0 + 8 < M)
                    *(__half2*)(Ch + (size_t)(row0 + 8) * NC + col) =
                        __floats2half2_rn(acc[t][u][2], acc[t][u][3]);
            } else {
                float* Cf = (float*)C;
                if (row0 < M)
                    *(float2*)(Cf + (size_t)row0 * NC + col) =
                        make_float2(acc[t][u][0], acc[t][u][1]);
                if (row0 + 8 < M)
                    *(float2*)(Cf + (size_t)(row0 + 8) * NC + col) =
                        make_float2(acc[t][u][2], acc[t][u][3]);
            }
        }
    }
}

// ---------------- batched weight transpose (fp32) ---------------------------
struct TPars {
    const float* src[10];
    int K[10], N[10], dstOff[10];
};
__global__ void k_transpose_all(TPars p) {
    const int m = blockIdx.y;
    const int K = p.K[m], Ncols = p.N[m];
    const float* src = p.src[m];
    float* dst = g_wt + p.dstOff[m];
    const int tot = K * Ncols;
    for (int i = blockIdx.x * blockDim.x + threadIdx.x; i < tot;
         i += gridDim.x * blockDim.x) {
        int k = i / Ncols, n = i % Ncols;
        dst[n * K + k] = src[i];
    }
}

// ---------------- edge dtype sniff -----------------------------------------
__global__ void k_detect(const int* e32) {
    __shared__ int nz;
    if (threadIdx.x == 0) nz = 0;
    __syncthreads();
    for (int i = threadIdx.x; i < 2048; i += blockDim.x) {
        if (e32[2 * i + 1] != 0) nz = 1;
    }
    __syncthreads();
    if (threadIdx.x == 0) g_fmt64 = (nz == 0) ? 1 : 0;
}

__device__ __forceinline__ int edge_at(const void* e, int idx) {
    if (g_fmt64) return (int)((const long long*)e)[idx];
    return ((const int*)e)[idx];
}

// ---------------- CSR build (2 views per launch) ----------------------------
struct EPtr4 { const void* e[4]; };

__global__ void k_zero_counts(int vbase) {
    int i = blockIdx.x * blockDim.x + threadIdx.x;
    if (i < NN) g_counts[vbase + blockIdx.y][i] = 0;
}

__global__ void k_count(EPtr4 ep, int vbase) {
    int i = blockIdx.x * blockDim.x + threadIdx.x;
    if (i >= EE) return;
    const int v = vbase + blockIdx.y;
    int d = edge_at(ep.e[v], EE + i);
    atomicAdd(&g_counts[v][d], 1);
}

__global__ void k_deg(int vbase) {
    int i = blockIdx.x * blockDim.x + threadIdx.x;
    if (i < NN) {
        int v = vbase + blockIdx.y;
        float dg = (float)(g_counts[v][i] + 1);
        g_dinv[v][i]   = rsqrtf(dg);
        g_deginv[v][i] = 1.0f / dg;
    }
}

__global__ void k_scan(int vbase) {
    const int v = vbase + blockIdx.x;
    __shared__ int sh[1024];
    __shared__ int carry;
    if (threadIdx.x == 0) { carry = 0; g_rowptr[v][0] = 0; }
    __syncthreads();
    for (int base = 0; base < NN; base += 1024) {
        int i = base + threadIdx.x;
        int val = (i < NN) ? g_counts[v][i] : 0;
        sh[threadIdx.x] = val;
        __syncthreads();
        for (int d = 1; d < 1024; d <<= 1) {
            int t = (threadIdx.x >= d) ? sh[threadIdx.x - d] : 0;
            __syncthreads();
            sh[threadIdx.x] += t;
            __syncthreads();
        }
        if (i < NN) {
            g_rowptr[v][i + 1] = carry + sh[threadIdx.x];
            g_cursor[v][i] = 0;
        }
        __syncthreads();
        if (threadIdx.x == 0) carry += sh[1023];
        __syncthreads();
    }
}

__global__ void k_fill(EPtr4 ep, int vbase) {
    int i = blockIdx.x * blockDim.x + threadIdx.x;
    if (i >= EE) return;
    const int v = vbase + blockIdx.y;
    int s = edge_at(ep.e[v], i);
    int d = edge_at(ep.e[v], EE + i);
    int pos = g_rowptr[v][d] + atomicAdd(&g_cursor[v][d], 1);
    g_col[v][pos]  = s;
    g_coef[v][pos] = g_dinv[v][s] * g_dinv[v][d];
}

// ---------------- agg1: fp16 gather -> fp32 hidden (F = 256) ----------------
// 32 threads/row (8 halves each), warp-uniform col/coef, 512B/warp/edge.
__global__ void __launch_bounds__(256)
k_agg16(const __half* __restrict__ xwAll, Ptr4 bias,
        float* __restrict__ outAll, int vbase) {
    const int view = vbase + blockIdx.y;
    const int rid = threadIdx.x >> 5;          // 8 rows per block
    const int f8  = threadIdx.x & 31;          // 8 features per thread
    const int row = blockIdx.x * 8 + rid;
    if (row >= NN) return;

    const __half* __restrict__ xw = xwAll + (size_t)view * NN * HID;
    float* __restrict__ out       = outAll + (size_t)view * NN * HID;
    const int* __restrict__ rp    = g_rowptr[view];
    const int* __restrict__ col   = g_col[view];
    const float* __restrict__ cf  = g_coef[view];

    const int start = rp[row];
    const int end   = rp[row + 1];
    float acc[8];
    #pragma unroll
    for (int i = 0; i < 8; i++) acc[i] = 0.f;

    #pragma unroll 2
    for (int p = start; p < end; p++) {
        const int s   = col[p];
        const float w = cf[p];
        uint4 v = *(const uint4*)(xw + (size_t)s * HID + f8 * 8);
        const __half2* hv = (const __half2*)&v;
        #pragma unroll
        for (int i = 0; i < 4; i++) {
            float2 f = __half22float2(hv[i]);
            acc[2 * i]     += f.x * w;
            acc[2 * i + 1] += f.y * w;
        }
    }

    const float di = g_deginv[view][row];
    uint4 sv = *(const uint4*)(xw + (size_t)row * HID + f8 * 8);
    const __half2* sh = (const __half2*)&sv;
    float4 b0 = *(const float4*)(bias.p[view] + f8 * 8);
    float4 b1 = *(const float4*)(bias.p[view] + f8 * 8 + 4);
    const float* bb = &b0.x;   // b0,b1 contiguous on stack? avoid: handle explicitly

    float o[8];
    #pragma unroll
    for (int i = 0; i < 4; i++) {
        float2 f = __half22float2(sh[i]);
        o[2 * i]     = acc[2 * i]     + f.x * di;
        o[2 * i + 1] = acc[2 * i + 1] + f.y * di;
    }
    o[0] += b0.x; o[1] += b0.y; o[2] += b0.z; o[3] += b0.w;
    o[4] += b1.x; o[5] += b1.y; o[6] += b1.z; o[7] += b1.w;
    #pragma unroll
    for (int i = 0; i < 8; i++) o[i] = (o[i] >= 0.f) ? o[i] : 0.2f * o[i];
    (void)bb;

    float4* dst = (float4*)(out + (size_t)row * HID + f8 * 8);
    dst[0] = make_float4(o[0], o[1], o[2], o[3]);
    dst[1] = make_float4(o[4], o[5], o[6], o[7]);
}

// ---------------- agg2: fp32 gather (F = 128) -------------------------------
template <int F>
__global__ void __launch_bounds__(256)
k_agg(const float* __restrict__ xwAll, Ptr4 bias, float* __restrict__ outAll,
      int vbase) {
    constexpr int TPR = F / 4;
    constexpr int RPB = 256 / TPR;
    const int view = vbase + blockIdx.y;
    const int rid = threadIdx.x / TPR;
    const int f4  = threadIdx.x % TPR;
    const int row = blockIdx.x * RPB + rid;
    if (row >= NN) return;

    const float* __restrict__ xw = xwAll + (size_t)view * NN * F;
    float* __restrict__ out      = outAll + (size_t)view * NN * F;
    const int* __restrict__ rp   = g_rowptr[view];
    const int* __restrict__ col  = g_col[view];
    const float* __restrict__ cf = g_coef[view];

    const int start = rp[row];
    const int end   = rp[row + 1];
    float4 acc = make_float4(0.f, 0.f, 0.f, 0.f);
    for (int p = start; p < end; p++) {
        const int s    = col[p];
        const float w  = cf[p];
        float4 v = *(const float4*)(xw + (size_t)s * F + f4 * 4);
        acc.x += v.x * w; acc.y += v.y * w;
        acc.z += v.z * w; acc.w += v.w * w;
    }
    const float di = g_deginv[view][row];
    float4 sv = *(const float4*)(xw + (size_t)row * F + f4 * 4);
    float4 bv = *(const float4*)(bias.p[view] + f4 * 4);
    float4 o;
    o.x = acc.x + sv.x * di + bv.x;
    o.y = acc.y + sv.y * di + bv.y;
    o.z = acc.z + sv.z * di + bv.z;
    o.w = acc.w + sv.w * di + bv.w;
    o.x = (o.x >= 0.f) ? o.x : 0.2f * o.x;
    o.y = (o.y >= 0.f) ? o.y : 0.2f * o.y;
    o.z = (o.z >= 0.f) ? o.z : 0.2f * o.z;
    o.w = (o.w >= 0.f) ? o.w : 0.2f * o.w;
    *(float4*)(out + (size_t)row * F + f4 * 4) = o;
}

// ---------------- final combine (batched over 2 node types) ----------------
struct CArgs { const float* res[2]; const float* rb[2]; };
__global__ void k_combine(const float* __restrict__ outSecs,
                          CArgs ca, float* __restrict__ dst) {
    const int j = blockIdx.y;
    const size_t SEC = (size_t)NN * FOUT;
    const float* jv  = outSecs + (2 + j) * SEC;
    const float* bv  = outSecs + (4 + j) * SEC;
    const float* res = ca.res[j];
    int i = blockIdx.x * blockDim.x + threadIdx.x;
    if (i < NN * FOUT) {
        dst[j * SEC + i] = 0.5f * (jv[i] + bv[i]) + res[i]
                         + ca.rb[j][i & (FOUT - 1)];
    }
}

// ---------------- host orchestration ----------------------------------------
#define GEMM_GRID_X ((NN + 127) / 128)

extern "C" void kernel_launch(void* const* d_in, const int* in_sizes, int n_in,
                              void* d_out, int out_size) {
    const float* x_lj = (const float*)d_in[0];
    const float* x_pj = (const float*)d_in[1];
    const float* x_lb = (const float*)d_in[2];
    const float* x_pb = (const float*)d_in[3];

    EPtr4 ep; ep.e[0] = d_in[4]; ep.e[1] = d_in[5]; ep.e[2] = d_in[6]; ep.e[3] = d_in[7];

    const float* W_j1_l = (const float*)d_in[8];   const float* b_j1_l = (const float*)d_in[9];
    const float* W_j1_p = (const float*)d_in[10];  const float* b_j1_p = (const float*)d_in[11];
    const float* W_j2_l = (const float*)d_in[12];  const float* b_j2_l = (const float*)d_in[13];
    const float* W_j2_p = (const float*)d_in[14];  const float* b_j2_p = (const float*)d_in[15];
    const float* W_b1_l = (const float*)d_in[16];  const float* b_b1_l = (const float*)d_in[17];
    const float* W_b1_p = (const float*)d_in[18];  const float* b_b1_p = (const float*)d_in[19];
    const float* W_b2_l = (const float*)d_in[20];  const float* b_b2_l = (const float*)d_in[21];
    const float* W_b2_p = (const float*)d_in[22];  const float* b_b2_p = (const float*)d_in[23];
    const float* W_r_l  = (const float*)d_in[24];  const float* b_r_l  = (const float*)d_in[25];
    const float* W_r_p  = (const float*)d_in[26];  const float* b_r_p  = (const float*)d_in[27];

    float* out = (float*)d_out;
    const size_t SEC = (size_t)NN * FOUT;

    float *bufA, *bufB, *bufC, *wt;
    __half* xwh;
    cudaGetSymbolAddress((void**)&bufA, g_bufA);
    cudaGetSymbolAddress((void**)&bufB, g_bufB);
    cudaGetSymbolAddress((void**)&bufC, g_bufC);
    cudaGetSymbolAddress((void**)&xwh,  g_xwh);
    cudaGetSymbolAddress((void**)&wt,   g_wt);

    cudaFuncSetAttribute((const void*)k_gemm<256, true>,
                         cudaFuncAttributeMaxDynamicSharedMemorySize, SMEM_GEMM);
    cudaFuncSetAttribute((const void*)k_gemm<128, false>,
                         cudaFuncAttributeMaxDynamicSharedMemorySize, SMEM_GEMM);

    cudaStream_t sB;
    cudaEvent_t eF, eT, eG1, eB;
    cudaStreamCreateWithFlags(&sB, cudaStreamNonBlocking);
    cudaEventCreateWithFlags(&eF,  cudaEventDisableTiming);
    cudaEventCreateWithFlags(&eT,  cudaEventDisableTiming);
    cudaEventCreateWithFlags(&eG1, cudaEventDisableTiming);
    cudaEventCreateWithFlags(&eB,  cudaEventDisableTiming);

    const size_t NHID = (size_t)NN * HID;
    const size_t NOUT = (size_t)NN * FOUT;
    dim3 gz2((NN + 255) / 256, 2);
    dim3 ge2((EE + 255) / 256, 2);

    const float* w2 = wt + 4 * 65536;

    // ---- stream 0: detect, fork B ----------------------------------------
    k_detect<<<1, 256>>>((const int*)ep.e[0]);
    cudaEventRecord(eF, 0);
    cudaStreamWaitEvent(sB, eF, 0);

    // ---- stream B: CSR for views 2,3 --------------------------------------
    k_zero_counts<<<gz2, 256, 0, sB>>>(2);
    k_count<<<ge2, 256, 0, sB>>>(ep, 2);
    k_deg<<<gz2, 256, 0, sB>>>(2);
    k_scan<<<2, 1024, 0, sB>>>(2);
    k_fill<<<ge2, 256, 0, sB>>>(ep, 2);

    // ---- stream 0 (pipeline A): weights + CSR(0,1) ------------------------
    TPars tp;
    const float* ws[10] = {W_j1_l, W_j1_p, W_b1_l, W_b1_p,
                           W_j2_l, W_j2_p, W_b2_l, W_b2_p, W_r_l, W_r_p};
    for (int m = 0; m < 10; m++) {
        tp.src[m] = ws[m];
        tp.K[m] = 256;
        tp.N[m] = (m < 4) ? 256 : 128;
        tp.dstOff[m] = (m < 4) ? m * 65536 : 4 * 65536 + (m - 4) * 32768;
    }
    k_transpose_all<<<dim3(64, 10), 256>>>(tp);
    cudaEventRecord(eT, 0);

    k_zero_counts<<<gz2, 256>>>(0);
    k_count<<<ge2, 256>>>(ep, 0);
    k_deg<<<gz2, 256>>>(0);
    k_scan<<<2, 1024>>>(0);
    k_fill<<<ge2, 256>>>(ep, 0);

    // ---- A: gemm1 (views 0,1) -> fp16 xwh ---------------------------------
    GArgs a1;
    a1.a[0] = x_lj;    a1.w[0] = wt;          a1.c[0] = xwh;
    a1.a[1] = x_pj;    a1.w[1] = wt + 65536;  a1.c[1] = xwh + NHID;
    a1.a[2] = a1.a[0]; a1.w[2] = a1.w[0];     a1.c[2] = a1.c[0];
    k_gemm<256, true><<<dim3(GEMM_GRID_X, 2, 2), 256, SMEM_GEMM>>>(a1, NN);
    cudaEventRecord(eG1, 0);

    // ---- B: gemm1 (views 2,3) — staggered ---------------------------------
    cudaStreamWaitEvent(sB, eT, 0);
    cudaStreamWaitEvent(sB, eG1, 0);
    GArgs b1g;
    b1g.a[0] = x_lb;    b1g.w[0] = wt + 2 * 65536;  b1g.c[0] = xwh + 2 * NHID;
    b1g.a[1] = x_pb;    b1g.w[1] = wt + 3 * 65536;  b1g.c[1] = xwh + 3 * NHID;
    b1g.a[2] = b1g.a[0]; b1g.w[2] = b1g.w[0];       b1g.c[2] = b1g.c[0];
    k_gemm<256, true><<<dim3(GEMM_GRID_X, 2, 2), 256, SMEM_GEMM, sB>>>(b1g, NN);

    // ---- A: agg1 (fp16 gather) --------------------------------------------
    Ptr4 bb1; bb1.p[0] = b_j1_l; bb1.p[1] = b_j1_p; bb1.p[2] = b_b1_l; bb1.p[3] = b_b1_p;
    k_agg16<<<dim3((NN + 7) / 8, 2), 256>>>(xwh, bb1, bufB, 0);

    // ---- B: agg1 ------------------------------------------------------------
    k_agg16<<<dim3((NN + 7) / 8, 2), 256, 0, sB>>>(xwh, bb1, bufB, 2);

    // ---- A: gemm2 + residual_l (z=3, fp32 out) ------------------------------
    GArgs a2;
    a2.a[0] = bufB;        a2.w[0] = w2;             a2.c[0] = bufC;
    a2.a[1] = bufB + NHID; a2.w[1] = w2 + 32768;     a2.c[1] = bufC + NOUT;
    a2.a[2] = x_lj;        a2.w[2] = w2 + 4 * 32768; a2.c[2] = bufA;   // res_l
    k_gemm<128, false><<<dim3(GEMM_GRID_X, 1, 3), 256, SMEM_GEMM>>>(a2, NN);

    // ---- B: gemm2 + residual_p ----------------------------------------------
    GArgs b2g;
    b2g.a[0] = bufB + 2 * NHID; b2g.w[0] = w2 + 2 * 32768; b2g.c[0] = bufC + 2 * NOUT;
    b2g.a[1] = bufB + 3 * NHID; b2g.w[1] = w2 + 3 * 32768; b2g.c[1] = bufC + 3 * NOUT;
    b2g.a[2] = x_pj;            b2g.w[2] = w2 + 5 * 32768; b2g.c[2] = bufA + 2 * NHID;
    k_gemm<128, false><<<dim3(GEMM_GRID_X, 1, 3), 256, SMEM_GEMM, sB>>>(b2g, NN);

    // ---- A: agg2 -> out sections 2,3 ----------------------------------------
    Ptr4 bb2; bb2.p[0] = b_j2_l; bb2.p[1] = b_j2_p; bb2.p[2] = b_b2_l; bb2.p[3] = b_b2_p;
    k_agg<FOUT><<<dim3((NN + 7) / 8, 2), 256>>>(bufC, bb2, out + 2 * SEC, 0);

    // ---- B: agg2 -> out sections 4,5 ----------------------------------------
    k_agg<FOUT><<<dim3((NN + 7) / 8, 2), 256, 0, sB>>>(bufC, bb2, out + 2 * SEC, 2);
    cudaEventRecord(eB, sB);

    // ---- join and combine ----------------------------------------------------
    cudaStreamWaitEvent(0, eB, 0);
    CArgs ca;
    ca.res[0] = bufA;
    ca.res[1] = bufA + 2 * NHID;
    ca.rb[0] = b_r_l; ca.rb[1] = b_r_p;
    k_combine<<<dim3((NN * FOUT + 255) / 256, 2), 256>>>(out, ca, out);
}

// round 13
// speedup vs baseline: 1.2229x; 1.0527x over previous
#include <cuda_runtime.h>
#include <cuda_bf16.h>
#include <cuda_fp16.h>
#include <cstdint>
#include <math.h>

#define NN   50000
#define EE   800000
#define FIN  256
#define HID  256
#define FOUT 128

// ---------------- scratch (device globals; no allocation allowed) ----------
__device__ float  g_bufB[4][NN * HID];   // hidden after agg1 (fp32)
__device__ __half g_xwh[4][NN * HID];    // gemm1 out (fp16) for agg1 gather
__device__ __half g_c2h[6][NN * FOUT];   // gemm2 out (0-3) + residuals (4,5), fp16
__device__ float  g_wt[4 * 65536 + 6 * 32768];  // transposed fp32 weights
__device__ float  g_dinv[4][NN];
__device__ float  g_deginv[4][NN];
__device__ int    g_counts[4][NN];
__device__ int    g_cursor[4][NN];
__device__ int    g_rowptr[4][NN + 1];
__device__ int    g_col[4][EE];
__device__ float  g_coef[4][EE];
__device__ int    g_fmt64;

struct Ptr4 { const float* p[4]; };

// ==================== helpers ================================================
__device__ __forceinline__ void cp16(uint32_t dst, const void* src, int nbytes) {
    asm volatile("cp.async.cg.shared.global [%0], [%1], 16, %2;"
                 :: "r"(dst), "l"(src), "r"(nbytes));
}

__device__ __forceinline__ void mma_bf16(float* d, const uint32_t* a, const uint32_t* b) {
    asm volatile(
        "mma.sync.aligned.m16n8k16.row.col.f32.bf16.bf16.f32 "
        "{%0,%1,%2,%3}, {%4,%5,%6,%7}, {%8,%9}, {%0,%1,%2,%3};"
        : "+f"(d[0]), "+f"(d[1]), "+f"(d[2]), "+f"(d[3])
        : "r"(a[0]), "r"(a[1]), "r"(a[2]), "r"(a[3]), "r"(b[0]), "r"(b[1]));
}

__device__ __forceinline__ uint32_t pack_bf16(float x, float y) {
    uint32_t r;
    asm("cvt.rn.bf16x2.f32 %0, %1, %2;" : "=r"(r) : "f"(y), "f"(x));
    return r;
}

__device__ __forceinline__ void split2(float2 v, uint32_t& hi, uint32_t& lo) {
    hi = pack_bf16(v.x, v.y);
    float h0 = __uint_as_float(hi << 16);
    float h1 = __uint_as_float(hi & 0xffff0000u);
    lo = pack_bf16(v.x - h0, v.y - h1);
}

__device__ __forceinline__ uint32_t smem_u32(const void* p) {
    uint32_t a;
    asm("{ .reg .u64 t; cvta.to.shared.u64 t, %1; cvt.u32.u64 %0, t; }"
        : "=r"(a) : "l"(p));
    return a;
}

// ==================== fused-split 3xBF16 GEMM ===============================
#define LDSA 40
#define BUF_FLOATS (128 * LDSA)
#define SMEM_GEMM (4 * BUF_FLOATS * 4)   // 81920 B

struct GArgs { const float *a[3], *w[3]; void* c[3]; };

template<int NC, bool HOUT>
__global__ void __launch_bounds__(256, 1)
k_gemm(GArgs g, int M)
{
    const int z = blockIdx.z;
    const float* __restrict__ A  = g.a[z];
    const float* __restrict__ Bt = g.w[z];
    void* __restrict__ C         = g.c[z];

    extern __shared__ float sm[];
    float* As = sm;
    float* Bs = sm + 2 * BUF_FLOATS;
    const uint32_t sA = smem_u32(As);
    const uint32_t sB = smem_u32(Bs);

    const int tid  = threadIdx.x;
    const int warp = tid >> 5, lane = tid & 31;
    const int wm = (warp & 3) * 32;
    const int wn = (warp >> 2) * 64;
    const int r  = lane >> 2, c = lane & 3;
    const int bm  = blockIdx.x * 128;
    const int bn0 = blockIdx.y * 128;

    const int lr0 = tid >> 3;
    const int lc4 = tid & 7;

    float acc[2][8][4];
    #pragma unroll
    for (int t = 0; t < 2; t++)
        #pragma unroll
        for (int u = 0; u < 8; u++)
            #pragma unroll
            for (int i = 0; i < 4; i++) acc[t][u][i] = 0.f;

    auto load_tile = [&](int kt, int buf) {
        const int k0 = kt * 32;
        #pragma unroll
        for (int i = 0; i < 4; i++) {
            const int row = lr0 + i * 32;
            const uint32_t soff = (uint32_t)((row * LDSA + lc4 * 4) * 4);
            const int grow = bm + row;
            const int rowok = (grow < M) ? grow : 0;
            cp16(sA + buf * (BUF_FLOATS * 4) + soff,
                 A + (size_t)rowok * 256 + k0 + lc4 * 4,
                 (grow < M) ? 16 : 0);
            cp16(sB + buf * (BUF_FLOATS * 4) + soff,
                 Bt + (size_t)(bn0 + row) * 256 + k0 + lc4 * 4, 16);
        }
    };

    load_tile(0, 0);
    asm volatile("cp.async.commit_group;" ::: "memory");
    load_tile(1, 1);
    asm volatile("cp.async.commit_group;" ::: "memory");

    #pragma unroll 1
    for (int kt = 0; kt < 8; kt++) {
        asm volatile("cp.async.wait_group 1;" ::: "memory");
        __syncthreads();

        const int buf = kt & 1;
        const float* Ab = As + buf * BUF_FLOATS;
        const float* Bb = Bs + buf * BUF_FLOATS;
        #pragma unroll
        for (int ks = 0; ks < 2; ks++) {
            const int kk = ks * 16;
            uint32_t afh[2][4], afl[2][4], bfh[8][2], bfl[8][2];
            #pragma unroll
            for (int t = 0; t < 2; t++) {
                const float* ap = Ab + (wm + t * 16 + r) * LDSA + kk + 2 * c;
                split2(*(const float2*)(ap),                afh[t][0], afl[t][0]);
                split2(*(const float2*)(ap + 8 * LDSA),     afh[t][1], afl[t][1]);
                split2(*(const float2*)(ap + 8),            afh[t][2], afl[t][2]);
                split2(*(const float2*)(ap + 8 * LDSA + 8), afh[t][3], afl[t][3]);
            }
            #pragma unroll
            for (int u = 0; u < 8; u++) {
                const float* bp = Bb + (wn + u * 8 + r) * LDSA + kk + 2 * c;
                split2(*(const float2*)(bp),     bfh[u][0], bfl[u][0]);
                split2(*(const float2*)(bp + 8), bfh[u][1], bfl[u][1]);
            }
            #pragma unroll
            for (int t = 0; t < 2; t++)
                #pragma unroll
                for (int u = 0; u < 8; u++) {
                    mma_bf16(acc[t][u], afl[t], bfh[u]);
                    mma_bf16(acc[t][u], afh[t], bfl[u]);
                    mma_bf16(acc[t][u], afh[t], bfh[u]);
                }
        }
        __syncthreads();
        if (kt + 2 < 8) load_tile(kt + 2, buf);
        asm volatile("cp.async.commit_group;" ::: "memory");
    }

    // ---- epilogue ----
    #pragma unroll
    for (int t = 0; t < 2; t++) {
        const int row0 = bm + wm + t * 16 + r;
        #pragma unroll
        for (int u = 0; u < 8; u++) {
            const int col = bn0 + wn + u * 8 + 2 * c;
            if (HOUT) {
                __half* Ch = (__half*)C;
                if (row0 < M)
                    *(__half2*)(Ch + (size_t)row0 * NC + col) =
                        __floats2half2_rn(acc[t][u][0], acc[t][u][1]);
                if (row0 + 8 < M)
                    *(__half2*)(Ch + (size_t)(row0 + 8) * NC + col) =
                        __floats2half2_rn(acc[t][u][2], acc[t][u][3]);
            } else {
                float* Cf = (float*)C;
                if (row0 < M)
                    *(float2*)(Cf + (size_t)row0 * NC + col) =
                        make_float2(acc[t][u][0], acc[t][u][1]);
                if (row0 + 8 < M)
                    *(float2*)(Cf + (size_t)(row0 + 8) * NC + col) =
                        make_float2(acc[t][u][2], acc[t][u][3]);
            }
        }
    }
}

// ---------------- batched weight transpose (fp32) ---------------------------
struct TPars {
    const float* src[10];
    int K[10], N[10], dstOff[10];
};
__global__ void k_transpose_all(TPars p) {
    const int m = blockIdx.y;
    const int K = p.K[m], Ncols = p.N[m];
    const float* src = p.src[m];
    float* dst = g_wt + p.dstOff[m];
    const int tot = K * Ncols;
    for (int i = blockIdx.x * blockDim.x + threadIdx.x; i < tot;
         i += gridDim.x * blockDim.x) {
        int k = i / Ncols, n = i % Ncols;
        dst[n * K + k] = src[i];
    }
}

// ---------------- edge dtype sniff -----------------------------------------
__global__ void k_detect(const int* e32) {
    __shared__ int nz;
    if (threadIdx.x == 0) nz = 0;
    __syncthreads();
    for (int i = threadIdx.x; i < 2048; i += blockDim.x) {
        if (e32[2 * i + 1] != 0) nz = 1;
    }
    __syncthreads();
    if (threadIdx.x == 0) g_fmt64 = (nz == 0) ? 1 : 0;
}

__device__ __forceinline__ int edge_at(const void* e, int idx) {
    if (g_fmt64) return (int)((const long long*)e)[idx];
    return ((const int*)e)[idx];
}

// ---------------- CSR build (2 views per launch) ----------------------------
struct EPtr4 { const void* e[4]; };

__global__ void k_zero_counts(int vbase) {
    int i = blockIdx.x * blockDim.x + threadIdx.x;
    if (i < NN) g_counts[vbase + blockIdx.y][i] = 0;
}

__global__ void k_count(EPtr4 ep, int vbase) {
    int i = blockIdx.x * blockDim.x + threadIdx.x;
    if (i >= EE) return;
    const int v = vbase + blockIdx.y;
    int d = edge_at(ep.e[v], EE + i);
    atomicAdd(&g_counts[v][d], 1);
}

__global__ void k_deg(int vbase) {
    int i = blockIdx.x * blockDim.x + threadIdx.x;
    if (i < NN) {
        int v = vbase + blockIdx.y;
        float dg = (float)(g_counts[v][i] + 1);
        g_dinv[v][i]   = rsqrtf(dg);
        g_deginv[v][i] = 1.0f / dg;
    }
}

__global__ void k_scan(int vbase) {
    const int v = vbase + blockIdx.x;
    __shared__ int sh[1024];
    __shared__ int carry;
    if (threadIdx.x == 0) { carry = 0; g_rowptr[v][0] = 0; }
    __syncthreads();
    for (int base = 0; base < NN; base += 1024) {
        int i = base + threadIdx.x;
        int val = (i < NN) ? g_counts[v][i] : 0;
        sh[threadIdx.x] = val;
        __syncthreads();
        for (int d = 1; d < 1024; d <<= 1) {
            int t = (threadIdx.x >= d) ? sh[threadIdx.x - d] : 0;
            __syncthreads();
            sh[threadIdx.x] += t;
            __syncthreads();
        }
        if (i < NN) {
            g_rowptr[v][i + 1] = carry + sh[threadIdx.x];
            g_cursor[v][i] = 0;
        }
        __syncthreads();
        if (threadIdx.x == 0) carry += sh[1023];
        __syncthreads();
    }
}

__global__ void k_fill(EPtr4 ep, int vbase) {
    int i = blockIdx.x * blockDim.x + threadIdx.x;
    if (i >= EE) return;
    const int v = vbase + blockIdx.y;
    int s = edge_at(ep.e[v], i);
    int d = edge_at(ep.e[v], EE + i);
    int pos = g_rowptr[v][d] + atomicAdd(&g_cursor[v][d], 1);
    g_col[v][pos]  = s;
    g_coef[v][pos] = g_dinv[v][s] * g_dinv[v][d];
}

// ---------------- agg: fp16 gather -> fp32 out + LeakyReLU ------------------
// F/8 threads per row, each thread 8 halves (uint4 = 16B).
template<int F>
__global__ void __launch_bounds__(256)
k_aggh(const __half* __restrict__ xwAll, Ptr4 bias,
       float* __restrict__ outAll, int vbase) {
    constexpr int TPH = F / 8;
    constexpr int RPB = 256 / TPH;
    const int view = vbase + blockIdx.y;
    const int rid = threadIdx.x / TPH;
    const int f8  = threadIdx.x % TPH;
    const int row = blockIdx.x * RPB + rid;
    if (row >= NN) return;

    const __half* __restrict__ xw = xwAll + (size_t)view * NN * F;
    float* __restrict__ out       = outAll + (size_t)view * NN * F;
    const int* __restrict__ rp    = g_rowptr[view];
    const int* __restrict__ col   = g_col[view];
    const float* __restrict__ cf  = g_coef[view];

    const int start = rp[row];
    const int end   = rp[row + 1];
    float acc[8];
    #pragma unroll
    for (int i = 0; i < 8; i++) acc[i] = 0.f;

    #pragma unroll 2
    for (int p = start; p < end; p++) {
        const int s   = col[p];
        const float w = cf[p];
        uint4 v = *(const uint4*)(xw + (size_t)s * F + f8 * 8);
        const __half2* hv = (const __half2*)&v;
        #pragma unroll
        for (int i = 0; i < 4; i++) {
            float2 f = __half22float2(hv[i]);
            acc[2 * i]     += f.x * w;
            acc[2 * i + 1] += f.y * w;
        }
    }

    const float di = g_deginv[view][row];
    uint4 sv = *(const uint4*)(xw + (size_t)row * F + f8 * 8);
    const __half2* sh = (const __half2*)&sv;
    float4 b0 = *(const float4*)(bias.p[view] + f8 * 8);
    float4 b1 = *(const float4*)(bias.p[view] + f8 * 8 + 4);

    float o[8];
    #pragma unroll
    for (int i = 0; i < 4; i++) {
        float2 f = __half22float2(sh[i]);
        o[2 * i]     = acc[2 * i]     + f.x * di;
        o[2 * i + 1] = acc[2 * i + 1] + f.y * di;
    }
    o[0] += b0.x; o[1] += b0.y; o[2] += b0.z; o[3] += b0.w;
    o[4] += b1.x; o[5] += b1.y; o[6] += b1.z; o[7] += b1.w;
    #pragma unroll
    for (int i = 0; i < 8; i++) o[i] = (o[i] >= 0.f) ? o[i] : 0.2f * o[i];

    float4* dst = (float4*)(out + (size_t)row * F + f8 * 8);
    dst[0] = make_float4(o[0], o[1], o[2], o[3]);
    dst[1] = make_float4(o[4], o[5], o[6], o[7]);
}

// ---------------- final combine (residual fp16) -----------------------------
struct CArgs { const __half* res[2]; const float* rb[2]; };
__global__ void k_combine(const float* __restrict__ outSecs,
                          CArgs ca, float* __restrict__ dst) {
    const int j = blockIdx.y;
    const size_t SEC = (size_t)NN * FOUT;
    const float* jv  = outSecs + (2 + j) * SEC;
    const float* bv  = outSecs + (4 + j) * SEC;
    const __half* res = ca.res[j];
    int i = blockIdx.x * blockDim.x + threadIdx.x;
    if (i < NN * FOUT) {
        dst[j * SEC + i] = 0.5f * (jv[i] + bv[i]) + __half2float(res[i])
                         + ca.rb[j][i & (FOUT - 1)];
    }
}

// ---------------- host orchestration ----------------------------------------
#define GEMM_GRID_X ((NN + 127) / 128)

extern "C" void kernel_launch(void* const* d_in, const int* in_sizes, int n_in,
                              void* d_out, int out_size) {
    const float* x_lj = (const float*)d_in[0];
    const float* x_pj = (const float*)d_in[1];
    const float* x_lb = (const float*)d_in[2];
    const float* x_pb = (const float*)d_in[3];

    EPtr4 ep; ep.e[0] = d_in[4]; ep.e[1] = d_in[5]; ep.e[2] = d_in[6]; ep.e[3] = d_in[7];

    const float* W_j1_l = (const float*)d_in[8];   const float* b_j1_l = (const float*)d_in[9];
    const float* W_j1_p = (const float*)d_in[10];  const float* b_j1_p = (const float*)d_in[11];
    const float* W_j2_l = (const float*)d_in[12];  const float* b_j2_l = (const float*)d_in[13];
    const float* W_j2_p = (const float*)d_in[14];  const float* b_j2_p = (const float*)d_in[15];
    const float* W_b1_l = (const float*)d_in[16];  const float* b_b1_l = (const float*)d_in[17];
    const float* W_b1_p = (const float*)d_in[18];  const float* b_b1_p = (const float*)d_in[19];
    const float* W_b2_l = (const float*)d_in[20];  const float* b_b2_l = (const float*)d_in[21];
    const float* W_b2_p = (const float*)d_in[22];  const float* b_b2_p = (const float*)d_in[23];
    const float* W_r_l  = (const float*)d_in[24];  const float* b_r_l  = (const float*)d_in[25];
    const float* W_r_p  = (const float*)d_in[26];  const float* b_r_p  = (const float*)d_in[27];

    float* out = (float*)d_out;
    const size_t SEC = (size_t)NN * FOUT;

    float *bufB, *wt;
    __half *xwh, *c2h;
    cudaGetSymbolAddress((void**)&bufB, g_bufB);
    cudaGetSymbolAddress((void**)&xwh,  g_xwh);
    cudaGetSymbolAddress((void**)&c2h,  g_c2h);
    cudaGetSymbolAddress((void**)&wt,   g_wt);

    cudaFuncSetAttribute((const void*)k_gemm<256, true>,
                         cudaFuncAttributeMaxDynamicSharedMemorySize, SMEM_GEMM);
    cudaFuncSetAttribute((const void*)k_gemm<128, true>,
                         cudaFuncAttributeMaxDynamicSharedMemorySize, SMEM_GEMM);

    cudaStream_t sB;
    cudaEvent_t eF, eT, eG1, eB;
    cudaStreamCreateWithFlags(&sB, cudaStreamNonBlocking);
    cudaEventCreateWithFlags(&eF,  cudaEventDisableTiming);
    cudaEventCreateWithFlags(&eT,  cudaEventDisableTiming);
    cudaEventCreateWithFlags(&eG1, cudaEventDisableTiming);
    cudaEventCreateWithFlags(&eB,  cudaEventDisableTiming);

    const size_t NHID = (size_t)NN * HID;
    const size_t NOUT = (size_t)NN * FOUT;
    dim3 gz2((NN + 255) / 256, 2);
    dim3 ge2((EE + 255) / 256, 2);

    const float* w2 = wt + 4 * 65536;

    // ---- stream 0: detect, fork B ----------------------------------------
    k_detect<<<1, 256>>>((const int*)ep.e[0]);
    cudaEventRecord(eF, 0);
    cudaStreamWaitEvent(sB, eF, 0);

    // ---- stream B: CSR for views 2,3 --------------------------------------
    k_zero_counts<<<gz2, 256, 0, sB>>>(2);
    k_count<<<ge2, 256, 0, sB>>>(ep, 2);
    k_deg<<<gz2, 256, 0, sB>>>(2);
    k_scan<<<2, 1024, 0, sB>>>(2);
    k_fill<<<ge2, 256, 0, sB>>>(ep, 2);

    // ---- stream 0 (pipeline A): weights + CSR(0,1) ------------------------
    TPars tp;
    const float* ws[10] = {W_j1_l, W_j1_p, W_b1_l, W_b1_p,
                           W_j2_l, W_j2_p, W_b2_l, W_b2_p, W_r_l, W_r_p};
    for (int m = 0; m < 10; m++) {
        tp.src[m] = ws[m];
        tp.K[m] = 256;
        tp.N[m] = (m < 4) ? 256 : 128;
        tp.dstOff[m] = (m < 4) ? m * 65536 : 4 * 65536 + (m - 4) * 32768;
    }
    k_transpose_all<<<dim3(64, 10), 256>>>(tp);
    cudaEventRecord(eT, 0);

    k_zero_counts<<<gz2, 256>>>(0);
    k_count<<<ge2, 256>>>(ep, 0);
    k_deg<<<gz2, 256>>>(0);
    k_scan<<<2, 1024>>>(0);
    k_fill<<<ge2, 256>>>(ep, 0);

    // ---- A: gemm1 (views 0,1) -> fp16 xwh ---------------------------------
    GArgs a1;
    a1.a[0] = x_lj;    a1.w[0] = wt;          a1.c[0] = xwh;
    a1.a[1] = x_pj;    a1.w[1] = wt + 65536;  a1.c[1] = xwh + NHID;
    a1.a[2] = a1.a[0]; a1.w[2] = a1.w[0];     a1.c[2] = a1.c[0];
    k_gemm<256, true><<<dim3(GEMM_GRID_X, 2, 2), 256, SMEM_GEMM>>>(a1, NN);
    cudaEventRecord(eG1, 0);

    // ---- B: gemm1 (views 2,3) — staggered ---------------------------------
    cudaStreamWaitEvent(sB, eT, 0);
    cudaStreamWaitEvent(sB, eG1, 0);
    GArgs b1g;
    b1g.a[0] = x_lb;    b1g.w[0] = wt + 2 * 65536;  b1g.c[0] = xwh + 2 * NHID;
    b1g.a[1] = x_pb;    b1g.w[1] = wt + 3 * 65536;  b1g.c[1] = xwh + 3 * NHID;
    b1g.a[2] = b1g.a[0]; b1g.w[2] = b1g.w[0];       b1g.c[2] = b1g.c[0];
    k_gemm<256, true><<<dim3(GEMM_GRID_X, 2, 2), 256, SMEM_GEMM, sB>>>(b1g, NN);

    // ---- A: agg1 (fp16 gather, F=256) -------------------------------------
    Ptr4 bb1; bb1.p[0] = b_j1_l; bb1.p[1] = b_j1_p; bb1.p[2] = b_b1_l; bb1.p[3] = b_b1_p;
    k_aggh<HID><<<dim3((NN + 7) / 8, 2), 256>>>(xwh, bb1, bufB, 0);

    // ---- B: agg1 ------------------------------------------------------------
    k_aggh<HID><<<dim3((NN + 7) / 8, 2), 256, 0, sB>>>(xwh, bb1, bufB, 2);

    // ---- A: gemm2 + residual_l (z=3, fp16 out) ------------------------------
    GArgs a2;
    a2.a[0] = bufB;        a2.w[0] = w2;             a2.c[0] = c2h;
    a2.a[1] = bufB + NHID; a2.w[1] = w2 + 32768;     a2.c[1] = c2h + NOUT;
    a2.a[2] = x_lj;        a2.w[2] = w2 + 4 * 32768; a2.c[2] = c2h + 4 * NOUT; // res_l
    k_gemm<128, true><<<dim3(GEMM_GRID_X, 1, 3), 256, SMEM_GEMM>>>(a2, NN);

    // ---- B: gemm2 + residual_p ----------------------------------------------
    GArgs b2g;
    b2g.a[0] = bufB + 2 * NHID; b2g.w[0] = w2 + 2 * 32768; b2g.c[0] = c2h + 2 * NOUT;
    b2g.a[1] = bufB + 3 * NHID; b2g.w[1] = w2 + 3 * 32768; b2g.c[1] = c2h + 3 * NOUT;
    b2g.a[2] = x_pj;            b2g.w[2] = w2 + 5 * 32768; b2g.c[2] = c2h + 5 * NOUT; // res_p
    k_gemm<128, true><<<dim3(GEMM_GRID_X, 1, 3), 256, SMEM_GEMM, sB>>>(b2g, NN);

    // ---- A: agg2 (fp16 gather, F=128) -> out sections 2,3 -------------------
    Ptr4 bb2; bb2.p[0] = b_j2_l; bb2.p[1] = b_j2_p; bb2.p[2] = b_b2_l; bb2.p[3] = b_b2_p;
    k_aggh<FOUT><<<dim3((NN + 15) / 16, 2), 256>>>(c2h, bb2, out + 2 * SEC, 0);

    // ---- B: agg2 -> out sections 4,5 ----------------------------------------
    k_aggh<FOUT><<<dim3((NN + 15) / 16, 2), 256, 0, sB>>>(c2h, bb2, out + 2 * SEC, 2);
    cudaEventRecord(eB, sB);

    // ---- join and combine ----------------------------------------------------
    cudaStreamWaitEvent(0, eB, 0);
    CArgs ca;
    ca.res[0] = c2h + 4 * NOUT;
    ca.res[1] = c2h + 5 * NOUT;
    ca.rb[0] = b_r_l; ca.rb[1] = b_r_p;
    k_combine<<<dim3((NN * FOUT + 255) / 256, 2), 256>>>(out, ca, out);
}